// round 4
// baseline (speedup 1.0000x reference)
#include <cuda_runtime.h>
#include <math.h>

#define BB   2
#define SS   2048
#define HH   2048
#define NHQ  32
#define NHKV 8
#define DK   64
#define DV   64
#define GQ   4          // NHQ / NHKV
#define QKV_OUT 3072    // NHQ*DK + NHKV*(DK+DV)
#define ATTN_SCALE 0.125f

// Scratch buffers (module-static device memory; allowed by harness rules)
__device__ float g_qkv [BB * SS * QKV_OUT];     // 50.3 MB
__device__ float g_attn[BB * SS * NHQ * DV];    // 33.6 MB

// ---------------------------------------------------------------------------
// Tiled FP32 GEMM: C[M,N] = A[M,K] @ B[K,N] (+ bias)
// 128x128 block tile, 8x8 per-thread microtile, 256 threads, k-step 8.
// Requires M%128==0, N%128==0, K%8==0 (true for all three calls).
// ---------------------------------------------------------------------------
template <bool BIAS>
__global__ __launch_bounds__(256)
void gemm128(const float* __restrict__ A, const float* __restrict__ B,
             float* __restrict__ C, const float* __restrict__ bias,
             int M, int N, int K)
{
    __shared__ float As[8][128];   // transposed: As[k][m]
    __shared__ float Bs[8][128];   // Bs[k][n]

    const int tid = threadIdx.x;
    const int tx  = tid & 15;       // 0..15 -> n (8 cols each)
    const int ty  = tid >> 4;       // 0..15 -> m (8 rows each)
    const int bn  = blockIdx.x * 128;
    const int bm  = blockIdx.y * 128;

    float acc[8][8] = {};

    for (int k0 = 0; k0 < K; k0 += 8) {
        // A tile: 128 rows x 8 cols. Each thread: one float4, stored transposed.
        {
            const int r  = tid >> 1;          // 0..127
            const int c4 = (tid & 1) * 4;     // 0 or 4
            float4 v = *reinterpret_cast<const float4*>(&A[(size_t)(bm + r) * K + k0 + c4]);
            As[c4 + 0][r] = v.x; As[c4 + 1][r] = v.y;
            As[c4 + 2][r] = v.z; As[c4 + 3][r] = v.w;
        }
        // B tile: 8 rows x 128 cols. Each thread: one float4.
        {
            const int r  = tid >> 5;          // 0..7
            const int c4 = (tid & 31) * 4;    // 0..124
            *reinterpret_cast<float4*>(&Bs[r][c4]) =
                *reinterpret_cast<const float4*>(&B[(size_t)(k0 + r) * N + bn + c4]);
        }
        __syncthreads();

        #pragma unroll
        for (int k = 0; k < 8; k++) {
            float a[8], b[8];
            *reinterpret_cast<float4*>(&a[0]) = *reinterpret_cast<const float4*>(&As[k][ty * 8]);
            *reinterpret_cast<float4*>(&a[4]) = *reinterpret_cast<const float4*>(&As[k][ty * 8 + 4]);
            *reinterpret_cast<float4*>(&b[0]) = *reinterpret_cast<const float4*>(&Bs[k][tx * 8]);
            *reinterpret_cast<float4*>(&b[4]) = *reinterpret_cast<const float4*>(&Bs[k][tx * 8 + 4]);
            #pragma unroll
            for (int i = 0; i < 8; i++)
                #pragma unroll
                for (int j = 0; j < 8; j++)
                    acc[i][j] += a[i] * b[j];
        }
        __syncthreads();
    }

    #pragma unroll
    for (int i = 0; i < 8; i++) {
        const int row = bm + ty * 8 + i;
        #pragma unroll
        for (int j4 = 0; j4 < 8; j4 += 4) {
            const int col = bn + tx * 8 + j4;
            float4 v;
            v.x = acc[i][j4 + 0];
            v.y = acc[i][j4 + 1];
            v.z = acc[i][j4 + 2];
            v.w = acc[i][j4 + 3];
            if (BIAS) {
                v.x += bias[col + 0]; v.y += bias[col + 1];
                v.z += bias[col + 2]; v.w += bias[col + 3];
            }
            *reinterpret_cast<float4*>(&C[(size_t)row * N + col]) = v;
        }
    }
}

// ---------------------------------------------------------------------------
// Causal flash attention (GQA). One block = 64 query rows of one (b, hq).
// One thread = one query row. K/V tiles (64x64 f32) staged in smem.
// Online softmax over 16-key sub-chunks (score array stays in registers).
// ---------------------------------------------------------------------------
__global__ __launch_bounds__(64)
void attn_kernel()
{
    __shared__ float Ks[64][64];
    __shared__ float Vs[64][64];

    const int tid = threadIdx.x;
    const int qt  = blockIdx.x;          // query tile (64 rows)
    const int bh  = blockIdx.y;          // b * NHQ + hq
    const int b   = bh >> 5;
    const int hq  = bh & 31;
    const int n   = hq >> 2;             // kv head
    const int qi  = qt * 64 + tid;       // global query index

    // Load q row (pre-scaled)
    float q[DK];
    {
        const float* qrow = &g_qkv[(size_t)(b * SS + qi) * QKV_OUT + hq * DK];
        #pragma unroll
        for (int d4 = 0; d4 < DK; d4 += 4) {
            float4 v = *reinterpret_cast<const float4*>(&qrow[d4]);
            q[d4 + 0] = v.x * ATTN_SCALE;
            q[d4 + 1] = v.y * ATTN_SCALE;
            q[d4 + 2] = v.z * ATTN_SCALE;
            q[d4 + 3] = v.w * ATTN_SCALE;
        }
    }

    float acc[DV];
    #pragma unroll
    for (int d = 0; d < DV; d++) acc[d] = 0.0f;
    float m = -INFINITY, l = 0.0f;

    const size_t koff = (size_t)NHQ * DK + (size_t)n * DK;          // 2048 + n*64
    const size_t voff = (size_t)NHQ * DK + (size_t)NHKV * DK + (size_t)n * DV;

    for (int kt = 0; kt <= qt; kt++) {
        __syncthreads();   // protect previous tile's smem consumers
        // Stage K and V tiles: 64 rows x 64 cols each, float4 loads
        {
            const float* kbase = &g_qkv[(size_t)(b * SS + kt * 64) * QKV_OUT + koff];
            const float* vbase = &g_qkv[(size_t)(b * SS + kt * 64) * QKV_OUT + voff];
            #pragma unroll
            for (int it = 0; it < 16; it++) {
                int i  = tid + it * 64;          // 0..1023
                int r  = i >> 4;                 // row 0..63
                int c4 = (i & 15) * 4;           // 0..60
                *reinterpret_cast<float4*>(&Ks[r][c4]) =
                    *reinterpret_cast<const float4*>(&kbase[(size_t)r * QKV_OUT + c4]);
                *reinterpret_cast<float4*>(&Vs[r][c4]) =
                    *reinterpret_cast<const float4*>(&vbase[(size_t)r * QKV_OUT + c4]);
            }
        }
        __syncthreads();

        const int qloc = qi - kt * 64;   // >= 0; key j valid iff j <= qloc
        #pragma unroll 1
        for (int sub = 0; sub < 4; sub++) {
            const int jbase = sub * 16;
            if (jbase > qloc) break;     // rest of tile fully masked (causal)

            float s[16];
            float mt = -INFINITY;
            #pragma unroll
            for (int jj = 0; jj < 16; jj++) {
                const int j = jbase + jj;
                float s0 = 0.f, s1 = 0.f, s2 = 0.f, s3 = 0.f;
                #pragma unroll
                for (int d4 = 0; d4 < DK; d4 += 4) {
                    float4 kv = *reinterpret_cast<const float4*>(&Ks[j][d4]);
                    s0 += q[d4 + 0] * kv.x;
                    s1 += q[d4 + 1] * kv.y;
                    s2 += q[d4 + 2] * kv.z;
                    s3 += q[d4 + 3] * kv.w;
                }
                float sv = (s0 + s1) + (s2 + s3);
                sv = (j <= qloc) ? sv : -INFINITY;
                s[jj] = sv;
                mt = fmaxf(mt, sv);
            }

            const float mnew = fmaxf(m, mt);
            const float corr = __expf(m - mnew);
            l *= corr;
            #pragma unroll
            for (int d = 0; d < DV; d++) acc[d] *= corr;

            #pragma unroll
            for (int jj = 0; jj < 16; jj++) {
                const float p = __expf(s[jj] - mnew);
                l += p;
                const int j = jbase + jj;
                #pragma unroll
                for (int d4 = 0; d4 < DV; d4 += 4) {
                    float4 vv = *reinterpret_cast<const float4*>(&Vs[j][d4]);
                    acc[d4 + 0] += p * vv.x;
                    acc[d4 + 1] += p * vv.y;
                    acc[d4 + 2] += p * vv.z;
                    acc[d4 + 3] += p * vv.w;
                }
            }
            m = mnew;
        }
    }

    const float inv = 1.0f / l;
    float* orow = &g_attn[(size_t)(b * SS + qi) * (NHQ * DV) + hq * DV];
    #pragma unroll
    for (int d4 = 0; d4 < DV; d4 += 4) {
        float4 v;
        v.x = acc[d4 + 0] * inv;
        v.y = acc[d4 + 1] * inv;
        v.z = acc[d4 + 2] * inv;
        v.w = acc[d4 + 3] * inv;
        *reinterpret_cast<float4*>(&orow[d4]) = v;
    }
}

// ---------------------------------------------------------------------------
// Launcher
// ---------------------------------------------------------------------------
extern "C" void kernel_launch(void* const* d_in, const int* in_sizes, int n_in,
                              void* d_out, int out_size)
{
    const float* x     = (const float*)d_in[0];   // (B,S,H)
    const float* Wqkv  = (const float*)d_in[1];   // (H, 3072)
    const float* Wout  = (const float*)d_in[2];   // (2048, H)
    const float* b_out = (const float*)d_in[3];   // (H,)
    // d_in[4] = mask: provably causal tril -> hardcoded
    float* out = (float*)d_out;

    float *qkv_ptr, *attn_ptr;
    cudaGetSymbolAddress((void**)&qkv_ptr,  g_qkv);
    cudaGetSymbolAddress((void**)&attn_ptr, g_attn);

    const int M = BB * SS;   // 4096

    // 1) QKV projection: (4096 x 2048) @ (2048 x 3072)
    {
        dim3 grid(QKV_OUT / 128, M / 128);
        gemm128<false><<<grid, 256>>>(x, Wqkv, qkv_ptr, nullptr, M, QKV_OUT, HH);
    }

    // 2) Causal GQA flash attention
    {
        dim3 grid(SS / 64, BB * NHQ);
        attn_kernel<<<grid, 64>>>();
    }

    // 3) Output projection + bias: (4096 x 2048) @ (2048 x 2048) + b
    {
        dim3 grid(HH / 128, M / 128);
        gemm128<true><<<grid, 256>>>(attn_ptr, Wout, out, b_out, M, HH, HH);
    }
}

// round 6
// speedup vs baseline: 1.3824x; 1.3824x over previous
#include <cuda_runtime.h>
#include <cuda_bf16.h>
#include <math.h>
#include <stdint.h>

#define BB   2
#define SS   2048
#define HH   2048
#define NHQ  32
#define NHKV 8
#define DK   64
#define DV   64
#define QKV_OUT 3072    // NHQ*DK + NHKV*(DK+DV)
#define ATTN_SCALE 0.125f
#define MM   (BB * SS)  // 4096

// ---------------------------------------------------------------------------
// Scratch (device globals; allocation APIs are forbidden)
// ---------------------------------------------------------------------------
__device__ float         g_qkv [BB * SS * QKV_OUT];          // fp32 QKV (50 MB)
__device__ float         g_attn[BB * SS * NHQ * DV];         // fp32 attn out (34 MB)
__device__ __nv_bfloat16 g_ah[MM * HH];                      // A hi (x or attn)
__device__ __nv_bfloat16 g_al[MM * HH];                      // A lo
__device__ __nv_bfloat16 g_wqh[QKV_OUT * HH];                // Wqkv^T hi  [N,K]
__device__ __nv_bfloat16 g_wql[QKV_OUT * HH];                // Wqkv^T lo
__device__ __nv_bfloat16 g_woh[HH * HH];                     // Wout^T hi  [N,K]
__device__ __nv_bfloat16 g_wol[HH * HH];                     // Wout^T lo

// ---------------------------------------------------------------------------
// Prep kernels: fp32 -> (bf16 hi, bf16 lo) split; optional transpose
// ---------------------------------------------------------------------------
__global__ __launch_bounds__(256)
void split_f32(const float* __restrict__ in, __nv_bfloat16* __restrict__ hi,
               __nv_bfloat16* __restrict__ lo, int n)
{
    int i = (blockIdx.x * blockDim.x + threadIdx.x) * 4;
    if (i >= n) return;
    float4 v = *reinterpret_cast<const float4*>(in + i);
    __nv_bfloat16 h0 = __float2bfloat16(v.x);
    __nv_bfloat16 h1 = __float2bfloat16(v.y);
    __nv_bfloat16 h2 = __float2bfloat16(v.z);
    __nv_bfloat16 h3 = __float2bfloat16(v.w);
    __nv_bfloat16 l0 = __float2bfloat16(v.x - __bfloat162float(h0));
    __nv_bfloat16 l1 = __float2bfloat16(v.y - __bfloat162float(h1));
    __nv_bfloat16 l2 = __float2bfloat16(v.z - __bfloat162float(h2));
    __nv_bfloat16 l3 = __float2bfloat16(v.w - __bfloat162float(h3));
    reinterpret_cast<__nv_bfloat162*>(hi + i)[0] = __nv_bfloat162(h0, h1);
    reinterpret_cast<__nv_bfloat162*>(hi + i)[1] = __nv_bfloat162(h2, h3);
    reinterpret_cast<__nv_bfloat162*>(lo + i)[0] = __nv_bfloat162(l0, l1);
    reinterpret_cast<__nv_bfloat162*>(lo + i)[1] = __nv_bfloat162(l2, l3);
}

// W[K,N] fp32 -> T[N,K] bf16 hi/lo (transposed split)
__global__ __launch_bounds__(256)
void transpose_split(const float* __restrict__ W, __nv_bfloat16* __restrict__ Th,
                     __nv_bfloat16* __restrict__ Tl, int K, int N)
{
    __shared__ float tile[32][33];
    const int n0 = blockIdx.x * 32;
    const int k0 = blockIdx.y * 32;
    const int tx = threadIdx.x;       // 0..31
    const int ty = threadIdx.y;       // 0..7
    #pragma unroll
    for (int r = ty; r < 32; r += 8)
        tile[r][tx] = W[(size_t)(k0 + r) * N + n0 + tx];
    __syncthreads();
    #pragma unroll
    for (int r = ty; r < 32; r += 8) {
        float a = tile[tx][r];                     // = W[k0+tx][n0+r]
        __nv_bfloat16 h = __float2bfloat16(a);
        __nv_bfloat16 l = __float2bfloat16(a - __bfloat162float(h));
        size_t o = (size_t)(n0 + r) * K + k0 + tx;
        Th[o] = h;
        Tl[o] = l;
    }
}

// ---------------------------------------------------------------------------
// HMMA (mma.sync m16n8k16 bf16) split GEMM:
//   C[M,N] = A[M,K] @ B^T (+bias), Bt is [N,K] K-major.
//   D = Ah*Bh + Ah*Bl + Al*Bh, fp32 accumulators in registers.
// CTA tile 128x128, K-chunk 32, 256 threads (8 warps, 2x4 warp grid,
// warp tile 64x32). Smem row stride padded to 40 bf16 (conflict-free).
// ---------------------------------------------------------------------------
#define SPAD 40

__device__ __forceinline__ void mma16816(float* d, const uint32_t* a, const uint32_t* b)
{
    asm volatile(
        "mma.sync.aligned.m16n8k16.row.col.f32.bf16.bf16.f32 "
        "{%0,%1,%2,%3}, {%4,%5,%6,%7}, {%8,%9}, {%0,%1,%2,%3};"
        : "+f"(d[0]), "+f"(d[1]), "+f"(d[2]), "+f"(d[3])
        : "r"(a[0]), "r"(a[1]), "r"(a[2]), "r"(a[3]), "r"(b[0]), "r"(b[1]));
}

__global__ __launch_bounds__(256)
void gemm_hmma(const __nv_bfloat16* __restrict__ Ah, const __nv_bfloat16* __restrict__ Al,
               const __nv_bfloat16* __restrict__ Bh, const __nv_bfloat16* __restrict__ Bl,
               float* __restrict__ C, const float* __restrict__ bias,
               int M, int N, int K, int hasBias)
{
    __shared__ __nv_bfloat16 sAh[128][SPAD];
    __shared__ __nv_bfloat16 sAl[128][SPAD];
    __shared__ __nv_bfloat16 sBh[128][SPAD];
    __shared__ __nv_bfloat16 sBl[128][SPAD];

    const int tid   = threadIdx.x;
    const int wid   = tid >> 5;
    const int lane  = tid & 31;
    const int wm    = (wid >> 2) * 64;    // warp M offset: 0 or 64
    const int wn    = (wid & 3) * 32;     // warp N offset: 0,32,64,96
    const int bm    = blockIdx.y * 128;
    const int bn    = blockIdx.x * 128;
    const int lrow  = lane >> 2;          // 0..7
    const int lkb   = (lane & 3) * 2;     // 0,2,4,6

    float acc[4][4][4];
    #pragma unroll
    for (int i = 0; i < 4; i++)
        #pragma unroll
        for (int j = 0; j < 4; j++)
            #pragma unroll
            for (int c = 0; c < 4; c++) acc[i][j][c] = 0.0f;

    for (int k0 = 0; k0 < K; k0 += 32) {
        // Stage 4 tiles (128 rows x 32 bf16 each) with uint4 (8 bf16) copies.
        #pragma unroll
        for (int i = 0; i < 2; i++) {
            const int idx = tid + i * 256;        // 0..511
            const int r   = idx >> 2;             // 0..127
            const int c8  = (idx & 3) * 8;        // bf16 col 0,8,16,24
            const size_t gA = (size_t)(bm + r) * K + k0 + c8;
            const size_t gB = (size_t)(bn + r) * K + k0 + c8;
            *reinterpret_cast<uint4*>(&sAh[r][c8]) = *reinterpret_cast<const uint4*>(Ah + gA);
            *reinterpret_cast<uint4*>(&sAl[r][c8]) = *reinterpret_cast<const uint4*>(Al + gA);
            *reinterpret_cast<uint4*>(&sBh[r][c8]) = *reinterpret_cast<const uint4*>(Bh + gB);
            *reinterpret_cast<uint4*>(&sBl[r][c8]) = *reinterpret_cast<const uint4*>(Bl + gB);
        }
        __syncthreads();

        #pragma unroll
        for (int ks = 0; ks < 2; ks++) {
            const int kb = ks * 16 + lkb;
            // A fragments for the 4 M-subtiles (hi and lo)
            uint32_t ah[4][4], al[4][4];
            #pragma unroll
            for (int mi = 0; mi < 4; mi++) {
                const int r0 = wm + mi * 16 + lrow;
                ah[mi][0] = *reinterpret_cast<const uint32_t*>(&sAh[r0    ][kb    ]);
                ah[mi][1] = *reinterpret_cast<const uint32_t*>(&sAh[r0 + 8][kb    ]);
                ah[mi][2] = *reinterpret_cast<const uint32_t*>(&sAh[r0    ][kb + 8]);
                ah[mi][3] = *reinterpret_cast<const uint32_t*>(&sAh[r0 + 8][kb + 8]);
                al[mi][0] = *reinterpret_cast<const uint32_t*>(&sAl[r0    ][kb    ]);
                al[mi][1] = *reinterpret_cast<const uint32_t*>(&sAl[r0 + 8][kb    ]);
                al[mi][2] = *reinterpret_cast<const uint32_t*>(&sAl[r0    ][kb + 8]);
                al[mi][3] = *reinterpret_cast<const uint32_t*>(&sAl[r0 + 8][kb + 8]);
            }
            #pragma unroll
            for (int ni = 0; ni < 4; ni++) {
                const int n0 = wn + ni * 8 + lrow;
                uint32_t bh[2], bl[2];
                bh[0] = *reinterpret_cast<const uint32_t*>(&sBh[n0][kb    ]);
                bh[1] = *reinterpret_cast<const uint32_t*>(&sBh[n0][kb + 8]);
                bl[0] = *reinterpret_cast<const uint32_t*>(&sBl[n0][kb    ]);
                bl[1] = *reinterpret_cast<const uint32_t*>(&sBl[n0][kb + 8]);
                #pragma unroll
                for (int mi = 0; mi < 4; mi++) {
                    mma16816(acc[mi][ni], ah[mi], bh);
                    mma16816(acc[mi][ni], ah[mi], bl);
                    mma16816(acc[mi][ni], al[mi], bh);
                }
            }
        }
        __syncthreads();
    }

    // Epilogue: D fragment c0,c1 -> (row, col..col+1); c2,c3 -> (row+8, ...)
    #pragma unroll
    for (int mi = 0; mi < 4; mi++) {
        const int r0 = bm + wm + mi * 16 + lrow;
        #pragma unroll
        for (int ni = 0; ni < 4; ni++) {
            const int col = bn + wn + ni * 8 + lkb;
            float b0 = 0.f, b1 = 0.f;
            if (hasBias) { b0 = bias[col]; b1 = bias[col + 1]; }
            float2 v0 = make_float2(acc[mi][ni][0] + b0, acc[mi][ni][1] + b1);
            float2 v1 = make_float2(acc[mi][ni][2] + b0, acc[mi][ni][3] + b1);
            *reinterpret_cast<float2*>(&C[(size_t)r0 * N + col])       = v0;
            *reinterpret_cast<float2*>(&C[(size_t)(r0 + 8) * N + col]) = v1;
        }
    }
}

// ---------------------------------------------------------------------------
// Causal flash attention (GQA) — unchanged from passing R4 kernel
// ---------------------------------------------------------------------------
__global__ __launch_bounds__(64)
void attn_kernel()
{
    __shared__ float Ks[64][64];
    __shared__ float Vs[64][64];

    const int tid = threadIdx.x;
    const int qt  = blockIdx.x;
    const int bh  = blockIdx.y;
    const int b   = bh >> 5;
    const int hq  = bh & 31;
    const int n   = hq >> 2;
    const int qi  = qt * 64 + tid;

    float q[DK];
    {
        const float* qrow = &g_qkv[(size_t)(b * SS + qi) * QKV_OUT + hq * DK];
        #pragma unroll
        for (int d4 = 0; d4 < DK; d4 += 4) {
            float4 v = *reinterpret_cast<const float4*>(&qrow[d4]);
            q[d4 + 0] = v.x * ATTN_SCALE;
            q[d4 + 1] = v.y * ATTN_SCALE;
            q[d4 + 2] = v.z * ATTN_SCALE;
            q[d4 + 3] = v.w * ATTN_SCALE;
        }
    }

    float acc[DV];
    #pragma unroll
    for (int d = 0; d < DV; d++) acc[d] = 0.0f;
    float m = -INFINITY, l = 0.0f;

    const size_t koff = (size_t)NHQ * DK + (size_t)n * DK;
    const size_t voff = (size_t)NHQ * DK + (size_t)NHKV * DK + (size_t)n * DV;

    for (int kt = 0; kt <= qt; kt++) {
        __syncthreads();
        {
            const float* kbase = &g_qkv[(size_t)(b * SS + kt * 64) * QKV_OUT + koff];
            const float* vbase = &g_qkv[(size_t)(b * SS + kt * 64) * QKV_OUT + voff];
            #pragma unroll
            for (int it = 0; it < 16; it++) {
                int i  = tid + it * 64;
                int r  = i >> 4;
                int c4 = (i & 15) * 4;
                *reinterpret_cast<float4*>(&Ks[r][c4]) =
                    *reinterpret_cast<const float4*>(&kbase[(size_t)r * QKV_OUT + c4]);
                *reinterpret_cast<float4*>(&Vs[r][c4]) =
                    *reinterpret_cast<const float4*>(&vbase[(size_t)r * QKV_OUT + c4]);
            }
        }
        __syncthreads();

        const int qloc = qi - kt * 64;
        #pragma unroll 1
        for (int sub = 0; sub < 4; sub++) {
            const int jbase = sub * 16;
            if (jbase > qloc) break;

            float s[16];
            float mt = -INFINITY;
            #pragma unroll
            for (int jj = 0; jj < 16; jj++) {
                const int j = jbase + jj;
                float s0 = 0.f, s1 = 0.f, s2 = 0.f, s3 = 0.f;
                #pragma unroll
                for (int d4 = 0; d4 < DK; d4 += 4) {
                    float4 kv = *reinterpret_cast<const float4*>(&Ks[j][d4]);
                    s0 += q[d4 + 0] * kv.x;
                    s1 += q[d4 + 1] * kv.y;
                    s2 += q[d4 + 2] * kv.z;
                    s3 += q[d4 + 3] * kv.w;
                }
                float sv = (s0 + s1) + (s2 + s3);
                sv = (j <= qloc) ? sv : -INFINITY;
                s[jj] = sv;
                mt = fmaxf(mt, sv);
            }

            const float mnew = fmaxf(m, mt);
            const float corr = __expf(m - mnew);
            l *= corr;
            #pragma unroll
            for (int d = 0; d < DV; d++) acc[d] *= corr;

            #pragma unroll
            for (int jj = 0; jj < 16; jj++) {
                const float p = __expf(s[jj] - mnew);
                l += p;
                const int j = jbase + jj;
                #pragma unroll
                for (int d4 = 0; d4 < DV; d4 += 4) {
                    float4 vv = *reinterpret_cast<const float4*>(&Vs[j][d4]);
                    acc[d4 + 0] += p * vv.x;
                    acc[d4 + 1] += p * vv.y;
                    acc[d4 + 2] += p * vv.z;
                    acc[d4 + 3] += p * vv.w;
                }
            }
            m = mnew;
        }
    }

    const float inv = 1.0f / l;
    float* orow = &g_attn[(size_t)(b * SS + qi) * (NHQ * DV) + hq * DV];
    #pragma unroll
    for (int d4 = 0; d4 < DV; d4 += 4) {
        float4 v;
        v.x = acc[d4 + 0] * inv;
        v.y = acc[d4 + 1] * inv;
        v.z = acc[d4 + 2] * inv;
        v.w = acc[d4 + 3] * inv;
        *reinterpret_cast<float4*>(&orow[d4]) = v;
    }
}

// ---------------------------------------------------------------------------
// Launcher
// ---------------------------------------------------------------------------
extern "C" void kernel_launch(void* const* d_in, const int* in_sizes, int n_in,
                              void* d_out, int out_size)
{
    const float* x     = (const float*)d_in[0];   // (B,S,H)
    const float* Wqkv  = (const float*)d_in[1];   // (H, 3072)
    const float* Wout  = (const float*)d_in[2];   // (2048, H)
    const float* b_out = (const float*)d_in[3];   // (H,)
    float* out = (float*)d_out;

    float *qkv_p, *attn_p;
    __nv_bfloat16 *ah_p, *al_p, *wqh_p, *wql_p, *woh_p, *wol_p;
    cudaGetSymbolAddress((void**)&qkv_p,  g_qkv);
    cudaGetSymbolAddress((void**)&attn_p, g_attn);
    cudaGetSymbolAddress((void**)&ah_p,   g_ah);
    cudaGetSymbolAddress((void**)&al_p,   g_al);
    cudaGetSymbolAddress((void**)&wqh_p,  g_wqh);
    cudaGetSymbolAddress((void**)&wql_p,  g_wql);
    cudaGetSymbolAddress((void**)&woh_p,  g_woh);
    cudaGetSymbolAddress((void**)&wol_p,  g_wol);

    // Prep: split x; transpose+split both weight matrices
    {
        const int n = MM * HH;
        split_f32<<<n / (256 * 4), 256>>>(x, ah_p, al_p, n);
    }
    transpose_split<<<dim3(QKV_OUT / 32, HH / 32), dim3(32, 8)>>>(Wqkv, wqh_p, wql_p, HH, QKV_OUT);
    transpose_split<<<dim3(HH / 32, HH / 32), dim3(32, 8)>>>(Wout, woh_p, wol_p, HH, HH);

    // 1) QKV projection (HMMA): (4096 x 2048) @ (2048 x 3072)
    gemm_hmma<<<dim3(QKV_OUT / 128, MM / 128), 256>>>(
        ah_p, al_p, wqh_p, wql_p, qkv_p, nullptr, MM, QKV_OUT, HH, 0);

    // 2) Causal GQA flash attention (fp32)
    attn_kernel<<<dim3(SS / 64, BB * NHQ), 64>>>();

    // 3) Split attn output, then output projection + bias (HMMA)
    {
        const int n = MM * HH;
        split_f32<<<n / (256 * 4), 256>>>(attn_p, ah_p, al_p, n);
    }
    gemm_hmma<<<dim3(HH / 128, MM / 128), 256>>>(
        ah_p, al_p, woh_p, wol_p, out, b_out, MM, HH, HH, 1);
}

// round 7
// speedup vs baseline: 2.8539x; 2.0645x over previous
#include <cuda_runtime.h>
#include <cuda_bf16.h>
#include <math.h>
#include <stdint.h>

#define BB   2
#define SS   2048
#define HH   2048
#define NHQ  32
#define NHKV 8
#define DK   64
#define DV   64
#define QKV_OUT 3072
#define ATTN_SCALE 0.125f
#define MM   (BB * SS)  // 4096

// ---------------------------------------------------------------------------
// Scratch (device globals)
// ---------------------------------------------------------------------------
__device__ float         g_qkv [BB * SS * QKV_OUT];          // fp32 QKV
__device__ __nv_bfloat16 g_ah[MM * HH];                      // A hi (x, then attn-out)
__device__ __nv_bfloat16 g_al[MM * HH];                      // A lo
__device__ __nv_bfloat16 g_wqh[QKV_OUT * HH];                // Wqkv^T hi [N,K]
__device__ __nv_bfloat16 g_wql[QKV_OUT * HH];
__device__ __nv_bfloat16 g_woh[HH * HH];                     // Wout^T hi [N,K]
__device__ __nv_bfloat16 g_wol[HH * HH];
// attention operands, pre-split bf16
__device__ __nv_bfloat16 g_qh [BB * NHQ  * SS * DK];         // [b][hq][s][d] (scaled)
__device__ __nv_bfloat16 g_ql [BB * NHQ  * SS * DK];
__device__ __nv_bfloat16 g_kh [BB * NHKV * SS * DK];         // [b][n][s][d]
__device__ __nv_bfloat16 g_kl [BB * NHKV * SS * DK];
__device__ __nv_bfloat16 g_vth[BB * NHKV * DV * SS];         // [b][n][d][s] (transposed)
__device__ __nv_bfloat16 g_vtl[BB * NHKV * DV * SS];

// ---------------------------------------------------------------------------
// Helpers
// ---------------------------------------------------------------------------
__device__ __forceinline__ uint32_t smem_to_u32(const void* p) {
    uint32_t a;
    asm("{ .reg .u64 t; cvta.to.shared.u64 t, %1; cvt.u32.u64 %0, t; }" : "=r"(a) : "l"(p));
    return a;
}
__device__ __forceinline__ void cp_async16(uint32_t dst, const void* src) {
    asm volatile("cp.async.cg.shared.global [%0], [%1], 16;" :: "r"(dst), "l"(src));
}
#define CP_COMMIT()  asm volatile("cp.async.commit_group;")
#define CP_WAIT1()   asm volatile("cp.async.wait_group 1;")
#define CP_WAIT0()   asm volatile("cp.async.wait_group 0;")

__device__ __forceinline__ void mma16816(float* d, const uint32_t* a, uint32_t b0, uint32_t b1)
{
    asm volatile(
        "mma.sync.aligned.m16n8k16.row.col.f32.bf16.bf16.f32 "
        "{%0,%1,%2,%3}, {%4,%5,%6,%7}, {%8,%9}, {%0,%1,%2,%3};"
        : "+f"(d[0]), "+f"(d[1]), "+f"(d[2]), "+f"(d[3])
        : "r"(a[0]), "r"(a[1]), "r"(a[2]), "r"(a[3]), "r"(b0), "r"(b1));
}

__device__ __forceinline__ void split_pack(float a, float b, uint32_t& hi, uint32_t& lo)
{
    __nv_bfloat16 ha = __float2bfloat16(a), hb = __float2bfloat16(b);
    __nv_bfloat16 la = __float2bfloat16(a - __bfloat162float(ha));
    __nv_bfloat16 lb = __float2bfloat16(b - __bfloat162float(hb));
    hi = ((uint32_t)__bfloat16_as_ushort(hb) << 16) | __bfloat16_as_ushort(ha);
    lo = ((uint32_t)__bfloat16_as_ushort(lb) << 16) | __bfloat16_as_ushort(la);
}

// ---------------------------------------------------------------------------
// Prep kernels
// ---------------------------------------------------------------------------
__global__ __launch_bounds__(256)
void split_f32(const float* __restrict__ in, __nv_bfloat16* __restrict__ hi,
               __nv_bfloat16* __restrict__ lo, int n)
{
    int i = (blockIdx.x * blockDim.x + threadIdx.x) * 4;
    if (i >= n) return;
    float4 v = *reinterpret_cast<const float4*>(in + i);
    uint32_t h0, l0, h1, l1;
    split_pack(v.x, v.y, h0, l0);
    split_pack(v.z, v.w, h1, l1);
    reinterpret_cast<uint32_t*>(hi + i)[0] = h0;
    reinterpret_cast<uint32_t*>(hi + i)[1] = h1;
    reinterpret_cast<uint32_t*>(lo + i)[0] = l0;
    reinterpret_cast<uint32_t*>(lo + i)[1] = l1;
}

// W[K,N] fp32 -> T[N,K] bf16 hi/lo
__global__ __launch_bounds__(256)
void transpose_split(const float* __restrict__ W, __nv_bfloat16* __restrict__ Th,
                     __nv_bfloat16* __restrict__ Tl, int K, int N)
{
    __shared__ float tile[32][33];
    const int n0 = blockIdx.x * 32;
    const int k0 = blockIdx.y * 32;
    const int tx = threadIdx.x;
    const int ty = threadIdx.y;
    #pragma unroll
    for (int r = ty; r < 32; r += 8)
        tile[r][tx] = W[(size_t)(k0 + r) * N + n0 + tx];
    __syncthreads();
    #pragma unroll
    for (int r = ty; r < 32; r += 8) {
        float a = tile[tx][r];
        __nv_bfloat16 h = __float2bfloat16(a);
        __nv_bfloat16 l = __float2bfloat16(a - __bfloat162float(h));
        size_t o = (size_t)(n0 + r) * K + k0 + tx;
        Th[o] = h;
        Tl[o] = l;
    }
}

// Q/K sections of g_qkv -> per-head bf16 hi/lo (Q scaled by ATTN_SCALE)
__global__ __launch_bounds__(256)
void split_qk()
{
    int idx = blockIdx.x * 256 + threadIdx.x;            // over 4096*2560/4
    int e   = idx * 4;
    int row = e / 2560;
    int col = e % 2560;
    if (row >= MM) return;
    int b = row >> 11, s = row & 2047;
    float4 v = *reinterpret_cast<const float4*>(&g_qkv[(size_t)row * QKV_OUT + col]);
    __nv_bfloat16 *dh, *dl;
    if (col < 2048) {
        int hq = col >> 6, d = col & 63;
        size_t o = ((size_t)(b * NHQ + hq) * SS + s) * DK + d;
        dh = g_qh + o; dl = g_ql + o;
        v.x *= ATTN_SCALE; v.y *= ATTN_SCALE; v.z *= ATTN_SCALE; v.w *= ATTN_SCALE;
    } else {
        int cc = col - 2048;
        int n = cc >> 6, d = cc & 63;
        size_t o = ((size_t)(b * NHKV + n) * SS + s) * DK + d;
        dh = g_kh + o; dl = g_kl + o;
    }
    uint32_t h0, l0, h1, l1;
    split_pack(v.x, v.y, h0, l0);
    split_pack(v.z, v.w, h1, l1);
    reinterpret_cast<uint32_t*>(dh)[0] = h0;
    reinterpret_cast<uint32_t*>(dh)[1] = h1;
    reinterpret_cast<uint32_t*>(dl)[0] = l0;
    reinterpret_cast<uint32_t*>(dl)[1] = l1;
}

// V section of g_qkv -> transposed [b][n][d][s] bf16 hi/lo
__global__ __launch_bounds__(256)
void transpose_split_v()
{
    __shared__ float tile[32][33];
    const int s0 = blockIdx.x * 32;
    const int d0 = blockIdx.y * 32;
    const int bz = blockIdx.z;           // b*8+n
    const int b  = bz >> 3, n = bz & 7;
    const int tx = threadIdx.x;
    const int ty = threadIdx.y;
    const int colbase = 2560 + n * 64 + d0;
    #pragma unroll
    for (int r = ty; r < 32; r += 8)
        tile[r][tx] = g_qkv[(size_t)(b * SS + s0 + r) * QKV_OUT + colbase + tx];
    __syncthreads();
    #pragma unroll
    for (int r = ty; r < 32; r += 8) {
        float a = tile[tx][r];           // = V[s0+tx][d0+r]
        __nv_bfloat16 h = __float2bfloat16(a);
        __nv_bfloat16 l = __float2bfloat16(a - __bfloat162float(h));
        size_t o = ((size_t)(b * NHKV + n) * DV + d0 + r) * SS + s0 + tx;
        g_vth[o] = h;
        g_vtl[o] = l;
    }
}

// ---------------------------------------------------------------------------
// HMMA split GEMM, cp.async double-buffered.
// C[M,N] = A[M,K] @ B^T (+bias); A,B pre-split bf16 hi/lo; Bt is [N,K].
// CTA 128x128, K-chunk 32, 2 stages, 256 threads.
// ---------------------------------------------------------------------------
#define SPAD 40
#define TILE_ELEMS (128 * SPAD)           // 5120 bf16 per tile
#define TILE_BYTES (TILE_ELEMS * 2)       // 10240
#define GSMEM_BYTES (TILE_BYTES * 8)      // 4 tiles x 2 stages = 81920

__global__ __launch_bounds__(256)
void gemm_hmma(const __nv_bfloat16* __restrict__ Ah, const __nv_bfloat16* __restrict__ Al,
               const __nv_bfloat16* __restrict__ Bh, const __nv_bfloat16* __restrict__ Bl,
               float* __restrict__ C, const float* __restrict__ bias,
               int M, int N, int K, int hasBias)
{
    extern __shared__ __nv_bfloat16 dsm[];
    const int tid  = threadIdx.x;
    const int wid  = tid >> 5;
    const int lane = tid & 31;
    const int wm   = (wid >> 2) * 64;
    const int wn   = (wid & 3) * 32;
    const int bm   = blockIdx.y * 128;
    const int bn   = blockIdx.x * 128;
    const int lrow = lane >> 2;
    const int lkb  = (lane & 3) * 2;
    const uint32_t sb = smem_to_u32(dsm);

    float acc[4][4][4];
    #pragma unroll
    for (int i = 0; i < 4; i++)
        #pragma unroll
        for (int j = 0; j < 4; j++)
            #pragma unroll
            for (int c = 0; c < 4; c++) acc[i][j][c] = 0.0f;

    const int nCh = K >> 5;

    auto issue = [&](int k0, int st) {
        #pragma unroll
        for (int i = 0; i < 2; i++) {
            const int idx = tid + i * 256;
            const int r   = idx >> 2;
            const int c8  = (idx & 3) * 8;
            const size_t gA = (size_t)(bm + r) * K + k0 + c8;
            const size_t gB = (size_t)(bn + r) * K + k0 + c8;
            const uint32_t so = (uint32_t)((r * SPAD + c8) * 2);
            cp_async16(sb + (0 * 2 + st) * TILE_BYTES + so, Ah + gA);
            cp_async16(sb + (1 * 2 + st) * TILE_BYTES + so, Al + gA);
            cp_async16(sb + (2 * 2 + st) * TILE_BYTES + so, Bh + gB);
            cp_async16(sb + (3 * 2 + st) * TILE_BYTES + so, Bl + gB);
        }
        CP_COMMIT();
    };

    issue(0, 0);
    for (int c = 0; c < nCh; c++) {
        if (c + 1 < nCh) { issue((c + 1) << 5, (c + 1) & 1); CP_WAIT1(); }
        else             { CP_WAIT0(); }
        __syncthreads();

        const __nv_bfloat16* sAh = dsm + (0 * 2 + (c & 1)) * TILE_ELEMS;
        const __nv_bfloat16* sAl = dsm + (1 * 2 + (c & 1)) * TILE_ELEMS;
        const __nv_bfloat16* sBh = dsm + (2 * 2 + (c & 1)) * TILE_ELEMS;
        const __nv_bfloat16* sBl = dsm + (3 * 2 + (c & 1)) * TILE_ELEMS;

        #pragma unroll
        for (int ks = 0; ks < 2; ks++) {
            const int kb = ks * 16 + lkb;
            uint32_t ah[4][4], al[4][4];
            #pragma unroll
            for (int mi = 0; mi < 4; mi++) {
                const int r0 = wm + mi * 16 + lrow;
                ah[mi][0] = *reinterpret_cast<const uint32_t*>(&sAh[r0 * SPAD + kb]);
                ah[mi][1] = *reinterpret_cast<const uint32_t*>(&sAh[(r0 + 8) * SPAD + kb]);
                ah[mi][2] = *reinterpret_cast<const uint32_t*>(&sAh[r0 * SPAD + kb + 8]);
                ah[mi][3] = *reinterpret_cast<const uint32_t*>(&sAh[(r0 + 8) * SPAD + kb + 8]);
                al[mi][0] = *reinterpret_cast<const uint32_t*>(&sAl[r0 * SPAD + kb]);
                al[mi][1] = *reinterpret_cast<const uint32_t*>(&sAl[(r0 + 8) * SPAD + kb]);
                al[mi][2] = *reinterpret_cast<const uint32_t*>(&sAl[r0 * SPAD + kb + 8]);
                al[mi][3] = *reinterpret_cast<const uint32_t*>(&sAl[(r0 + 8) * SPAD + kb + 8]);
            }
            #pragma unroll
            for (int ni = 0; ni < 4; ni++) {
                const int n0 = wn + ni * 8 + lrow;
                uint32_t bh0 = *reinterpret_cast<const uint32_t*>(&sBh[n0 * SPAD + kb]);
                uint32_t bh1 = *reinterpret_cast<const uint32_t*>(&sBh[n0 * SPAD + kb + 8]);
                uint32_t bl0 = *reinterpret_cast<const uint32_t*>(&sBl[n0 * SPAD + kb]);
                uint32_t bl1 = *reinterpret_cast<const uint32_t*>(&sBl[n0 * SPAD + kb + 8]);
                #pragma unroll
                for (int mi = 0; mi < 4; mi++) {
                    mma16816(acc[mi][ni], ah[mi], bh0, bh1);
                    mma16816(acc[mi][ni], ah[mi], bl0, bl1);
                    mma16816(acc[mi][ni], al[mi], bh0, bh1);
                }
            }
        }
        __syncthreads();
    }

    #pragma unroll
    for (int mi = 0; mi < 4; mi++) {
        const int r0 = bm + wm + mi * 16 + lrow;
        #pragma unroll
        for (int ni = 0; ni < 4; ni++) {
            const int col = bn + wn + ni * 8 + lkb;
            float b0 = 0.f, b1 = 0.f;
            if (hasBias) { b0 = bias[col]; b1 = bias[col + 1]; }
            float2 v0 = make_float2(acc[mi][ni][0] + b0, acc[mi][ni][1] + b1);
            float2 v1 = make_float2(acc[mi][ni][2] + b0, acc[mi][ni][3] + b1);
            *reinterpret_cast<float2*>(&C[(size_t)r0 * N + col])       = v0;
            *reinterpret_cast<float2*>(&C[(size_t)(r0 + 8) * N + col]) = v1;
        }
    }
}

// ---------------------------------------------------------------------------
// Tensor-core causal flash attention (GQA), split-bf16 (3-MMA) for both
// QK^T and PV. 128 threads, 64-query tile per block.
// Writes output split hi/lo directly into g_ah/g_al for gemm2.
// ---------------------------------------------------------------------------
#define APAD 72

__global__ __launch_bounds__(128)
void attn_tc()
{
    __shared__ __nv_bfloat16 sKh[64][APAD];
    __shared__ __nv_bfloat16 sKl[64][APAD];
    __shared__ __nv_bfloat16 sVh[64][APAD];   // V^T: [dv][key]
    __shared__ __nv_bfloat16 sVl[64][APAD];

    const int tid  = threadIdx.x;
    const int wid  = tid >> 5;
    const int lane = tid & 31;
    const int g    = lane >> 2;
    const int tig  = lane & 3;
    const int qt   = (int)gridDim.x - 1 - (int)blockIdx.x;   // heavy tiles first
    const int bh   = blockIdx.y;
    const int b    = bh >> 5;
    const int hq   = bh & 31;
    const int n    = hq >> 2;
    const int wm   = wid * 16;

    // --- stage Q tile (64x64 hi/lo) via sKh/sKl, then load fragments ---
    const __nv_bfloat16* qhb = g_qh + ((size_t)(b * NHQ + hq) * SS + qt * 64) * DK;
    const __nv_bfloat16* qlb = g_ql + ((size_t)(b * NHQ + hq) * SS + qt * 64) * DK;
    #pragma unroll
    for (int it = 0; it < 4; it++) {
        const int idx = it * 128 + tid;
        const int r = idx >> 3, c8 = (idx & 7) * 8;
        *reinterpret_cast<uint4*>(&sKh[r][c8]) = *reinterpret_cast<const uint4*>(qhb + r * DK + c8);
        *reinterpret_cast<uint4*>(&sKl[r][c8]) = *reinterpret_cast<const uint4*>(qlb + r * DK + c8);
    }
    __syncthreads();
    uint32_t qh[4][4], ql[4][4];
    #pragma unroll
    for (int ks = 0; ks < 4; ks++) {
        const int r0 = wm + g;
        const int kb = ks * 16 + tig * 2;
        qh[ks][0] = *reinterpret_cast<const uint32_t*>(&sKh[r0][kb]);
        qh[ks][1] = *reinterpret_cast<const uint32_t*>(&sKh[r0 + 8][kb]);
        qh[ks][2] = *reinterpret_cast<const uint32_t*>(&sKh[r0][kb + 8]);
        qh[ks][3] = *reinterpret_cast<const uint32_t*>(&sKh[r0 + 8][kb + 8]);
        ql[ks][0] = *reinterpret_cast<const uint32_t*>(&sKl[r0][kb]);
        ql[ks][1] = *reinterpret_cast<const uint32_t*>(&sKl[r0 + 8][kb]);
        ql[ks][2] = *reinterpret_cast<const uint32_t*>(&sKl[r0][kb + 8]);
        ql[ks][3] = *reinterpret_cast<const uint32_t*>(&sKl[r0 + 8][kb + 8]);
    }

    float oacc[8][4];
    #pragma unroll
    for (int i = 0; i < 8; i++)
        #pragma unroll
        for (int c = 0; c < 4; c++) oacc[i][c] = 0.0f;
    float m0 = -INFINITY, m1 = -INFINITY, l0 = 0.0f, l1 = 0.0f;

    const __nv_bfloat16* khb = g_kh  + (size_t)(b * NHKV + n) * SS * DK;
    const __nv_bfloat16* klb = g_kl  + (size_t)(b * NHKV + n) * SS * DK;
    const __nv_bfloat16* vhb = g_vth + (size_t)(b * NHKV + n) * DV * SS;
    const __nv_bfloat16* vlb = g_vtl + (size_t)(b * NHKV + n) * DV * SS;

    for (int kt = 0; kt <= qt; kt++) {
        __syncthreads();
        #pragma unroll
        for (int it = 0; it < 4; it++) {
            const int idx = it * 128 + tid;
            const int r = idx >> 3, c8 = (idx & 7) * 8;
            *reinterpret_cast<uint4*>(&sKh[r][c8]) =
                *reinterpret_cast<const uint4*>(khb + (size_t)(kt * 64 + r) * DK + c8);
            *reinterpret_cast<uint4*>(&sKl[r][c8]) =
                *reinterpret_cast<const uint4*>(klb + (size_t)(kt * 64 + r) * DK + c8);
            *reinterpret_cast<uint4*>(&sVh[r][c8]) =
                *reinterpret_cast<const uint4*>(vhb + (size_t)r * SS + kt * 64 + c8);
            *reinterpret_cast<uint4*>(&sVl[r][c8]) =
                *reinterpret_cast<const uint4*>(vlb + (size_t)r * SS + kt * 64 + c8);
        }
        __syncthreads();

        // ---- S = Q K^T (split 3-mma), fp32 fragments ----
        float sacc[8][4];
        #pragma unroll
        for (int i = 0; i < 8; i++)
            #pragma unroll
            for (int c = 0; c < 4; c++) sacc[i][c] = 0.0f;

        #pragma unroll
        for (int ni = 0; ni < 8; ni++) {
            const int kr = ni * 8 + g;
            #pragma unroll
            for (int ks = 0; ks < 4; ks++) {
                const int kb = ks * 16 + tig * 2;
                uint32_t kh0 = *reinterpret_cast<const uint32_t*>(&sKh[kr][kb]);
                uint32_t kh1 = *reinterpret_cast<const uint32_t*>(&sKh[kr][kb + 8]);
                uint32_t kl0 = *reinterpret_cast<const uint32_t*>(&sKl[kr][kb]);
                uint32_t kl1 = *reinterpret_cast<const uint32_t*>(&sKl[kr][kb + 8]);
                mma16816(sacc[ni], qh[ks], kh0, kh1);
                mma16816(sacc[ni], qh[ks], kl0, kl1);
                mma16816(sacc[ni], ql[ks], kh0, kh1);
            }
        }

        // ---- causal mask (diagonal tile only) ----
        if (kt == qt) {
            #pragma unroll
            for (int ni = 0; ni < 8; ni++) {
                #pragma unroll
                for (int c = 0; c < 4; c++) {
                    const int jl = ni * 8 + tig * 2 + (c & 1);
                    const int il = wm + g + ((c & 2) ? 8 : 0);
                    if (jl > il) sacc[ni][c] = -INFINITY;
                }
            }
        }

        // ---- online softmax ----
        float rmax0 = -INFINITY, rmax1 = -INFINITY;
        #pragma unroll
        for (int ni = 0; ni < 8; ni++) {
            rmax0 = fmaxf(rmax0, fmaxf(sacc[ni][0], sacc[ni][1]));
            rmax1 = fmaxf(rmax1, fmaxf(sacc[ni][2], sacc[ni][3]));
        }
        rmax0 = fmaxf(rmax0, __shfl_xor_sync(0xffffffffu, rmax0, 1));
        rmax0 = fmaxf(rmax0, __shfl_xor_sync(0xffffffffu, rmax0, 2));
        rmax1 = fmaxf(rmax1, __shfl_xor_sync(0xffffffffu, rmax1, 1));
        rmax1 = fmaxf(rmax1, __shfl_xor_sync(0xffffffffu, rmax1, 2));

        const float mn0 = fmaxf(m0, rmax0);
        const float mn1 = fmaxf(m1, rmax1);
        const float cr0 = __expf(m0 - mn0);
        const float cr1 = __expf(m1 - mn1);
        float rs0 = 0.0f, rs1 = 0.0f;
        #pragma unroll
        for (int ni = 0; ni < 8; ni++) {
            float p0 = __expf(sacc[ni][0] - mn0);
            float p1 = __expf(sacc[ni][1] - mn0);
            float p2 = __expf(sacc[ni][2] - mn1);
            float p3 = __expf(sacc[ni][3] - mn1);
            sacc[ni][0] = p0; sacc[ni][1] = p1; sacc[ni][2] = p2; sacc[ni][3] = p3;
            rs0 += p0 + p1;
            rs1 += p2 + p3;
        }
        rs0 += __shfl_xor_sync(0xffffffffu, rs0, 1);
        rs0 += __shfl_xor_sync(0xffffffffu, rs0, 2);
        rs1 += __shfl_xor_sync(0xffffffffu, rs1, 1);
        rs1 += __shfl_xor_sync(0xffffffffu, rs1, 2);
        l0 = l0 * cr0 + rs0;
        l1 = l1 * cr1 + rs1;
        m0 = mn0; m1 = mn1;
        #pragma unroll
        for (int ni = 0; ni < 8; ni++) {
            oacc[ni][0] *= cr0; oacc[ni][1] *= cr0;
            oacc[ni][2] *= cr1; oacc[ni][3] *= cr1;
        }

        // ---- O += P V (split 3-mma); P fragments built per k-step ----
        #pragma unroll
        for (int ks = 0; ks < 4; ks++) {
            uint32_t ph[4], pl[4];
            split_pack(sacc[2 * ks][0],     sacc[2 * ks][1],     ph[0], pl[0]);
            split_pack(sacc[2 * ks][2],     sacc[2 * ks][3],     ph[1], pl[1]);
            split_pack(sacc[2 * ks + 1][0], sacc[2 * ks + 1][1], ph[2], pl[2]);
            split_pack(sacc[2 * ks + 1][2], sacc[2 * ks + 1][3], ph[3], pl[3]);
            #pragma unroll
            for (int ni = 0; ni < 8; ni++) {
                const int vr = ni * 8 + g;
                const int kk = ks * 16 + tig * 2;
                uint32_t vh0 = *reinterpret_cast<const uint32_t*>(&sVh[vr][kk]);
                uint32_t vh1 = *reinterpret_cast<const uint32_t*>(&sVh[vr][kk + 8]);
                uint32_t vl0 = *reinterpret_cast<const uint32_t*>(&sVl[vr][kk]);
                uint32_t vl1 = *reinterpret_cast<const uint32_t*>(&sVl[vr][kk + 8]);
                mma16816(oacc[ni], ph, vh0, vh1);
                mma16816(oacc[ni], ph, vl0, vl1);
                mma16816(oacc[ni], pl, vh0, vh1);
            }
        }
    }

    // ---- epilogue: normalize + split hi/lo directly into gemm2 A buffers ----
    const float inv0 = 1.0f / l0;
    const float inv1 = 1.0f / l1;
    const size_t r0g = (size_t)(b * SS + qt * 64 + wm + g);
    const size_t r1g = r0g + 8;
    #pragma unroll
    for (int ni = 0; ni < 8; ni++) {
        const int col = hq * DV + ni * 8 + tig * 2;
        uint32_t hi, lo;
        split_pack(oacc[ni][0] * inv0, oacc[ni][1] * inv0, hi, lo);
        *reinterpret_cast<uint32_t*>(&g_ah[r0g * HH + col]) = hi;
        *reinterpret_cast<uint32_t*>(&g_al[r0g * HH + col]) = lo;
        split_pack(oacc[ni][2] * inv1, oacc[ni][3] * inv1, hi, lo);
        *reinterpret_cast<uint32_t*>(&g_ah[r1g * HH + col]) = hi;
        *reinterpret_cast<uint32_t*>(&g_al[r1g * HH + col]) = lo;
    }
}

// ---------------------------------------------------------------------------
// Launcher
// ---------------------------------------------------------------------------
extern "C" void kernel_launch(void* const* d_in, const int* in_sizes, int n_in,
                              void* d_out, int out_size)
{
    const float* x     = (const float*)d_in[0];
    const float* Wqkv  = (const float*)d_in[1];
    const float* Wout  = (const float*)d_in[2];
    const float* b_out = (const float*)d_in[3];
    float* out = (float*)d_out;

    float* qkv_p;
    __nv_bfloat16 *ah_p, *al_p, *wqh_p, *wql_p, *woh_p, *wol_p;
    cudaGetSymbolAddress((void**)&qkv_p, g_qkv);
    cudaGetSymbolAddress((void**)&ah_p,  g_ah);
    cudaGetSymbolAddress((void**)&al_p,  g_al);
    cudaGetSymbolAddress((void**)&wqh_p, g_wqh);
    cudaGetSymbolAddress((void**)&wql_p, g_wql);
    cudaGetSymbolAddress((void**)&woh_p, g_woh);
    cudaGetSymbolAddress((void**)&wol_p, g_wol);

    cudaFuncSetAttribute(gemm_hmma, cudaFuncAttributeMaxDynamicSharedMemorySize,
                         GSMEM_BYTES);

    // Prep: split x; transpose+split weights
    {
        const int n = MM * HH;
        split_f32<<<n / (256 * 4), 256>>>(x, ah_p, al_p, n);
    }
    transpose_split<<<dim3(QKV_OUT / 32, HH / 32), dim3(32, 8)>>>(Wqkv, wqh_p, wql_p, HH, QKV_OUT);
    transpose_split<<<dim3(HH / 32, HH / 32), dim3(32, 8)>>>(Wout, woh_p, wol_p, HH, HH);

    // 1) QKV projection
    gemm_hmma<<<dim3(QKV_OUT / 128, MM / 128), 256, GSMEM_BYTES>>>(
        ah_p, al_p, wqh_p, wql_p, qkv_p, nullptr, MM, QKV_OUT, HH, 0);

    // 2) Split Q/K (scaled) and transpose-split V
    split_qk<<<(MM * 2560 / 4) / 256, 256>>>();
    transpose_split_v<<<dim3(SS / 32, DV / 32, BB * NHKV), dim3(32, 8)>>>();

    // 3) Tensor-core flash attention -> writes g_ah/g_al
    attn_tc<<<dim3(SS / 64, BB * NHQ), 128>>>();

    // 4) Output projection + bias
    gemm_hmma<<<dim3(HH / 128, MM / 128), 256, GSMEM_BYTES>>>(
        ah_p, al_p, woh_p, wol_p, out, b_out, MM, HH, HH, 1);
}

// round 9
// speedup vs baseline: 3.1027x; 1.0872x over previous
#include <cuda_runtime.h>
#include <cuda_bf16.h>
#include <math.h>
#include <stdint.h>

#define BB   2
#define SS   2048
#define HH   2048
#define NHQ  32
#define NHKV 8
#define DK   64
#define DV   64
#define QKV_OUT 3072
#define ATTN_SCALE 0.125f
#define MM   (BB * SS)  // 4096

// ---------------------------------------------------------------------------
// Scratch (device globals)
// ---------------------------------------------------------------------------
__device__ float         g_qkv [BB * SS * QKV_OUT];          // fp32 QKV
__device__ __nv_bfloat16 g_ah[MM * HH];                      // A hi (x, then attn-out)
__device__ __nv_bfloat16 g_al[MM * HH];                      // A lo
__device__ __nv_bfloat16 g_wqh[QKV_OUT * HH];                // Wqkv^T hi [N,K]
__device__ __nv_bfloat16 g_wql[QKV_OUT * HH];
__device__ __nv_bfloat16 g_woh[HH * HH];                     // Wout^T hi [N,K]
__device__ __nv_bfloat16 g_wol[HH * HH];
// attention operands, pre-split bf16
__device__ __nv_bfloat16 g_qh [BB * NHQ  * SS * DK];         // [b][hq][s][d] (scaled)
__device__ __nv_bfloat16 g_ql [BB * NHQ  * SS * DK];
__device__ __nv_bfloat16 g_kh [BB * NHKV * SS * DK];         // [b][n][s][d]
__device__ __nv_bfloat16 g_kl [BB * NHKV * SS * DK];
__device__ __nv_bfloat16 g_vth[BB * NHKV * DV * SS];         // [b][n][d][s] (transposed)
__device__ __nv_bfloat16 g_vtl[BB * NHKV * DV * SS];

// ---------------------------------------------------------------------------
// Helpers
// ---------------------------------------------------------------------------
__device__ __forceinline__ uint32_t smem_to_u32(const void* p) {
    uint32_t a;
    asm("{ .reg .u64 t; cvta.to.shared.u64 t, %1; cvt.u32.u64 %0, t; }" : "=r"(a) : "l"(p));
    return a;
}
__device__ __forceinline__ void cp_async16(uint32_t dst, const void* src) {
    asm volatile("cp.async.cg.shared.global [%0], [%1], 16;" :: "r"(dst), "l"(src));
}
#define CP_COMMIT()  asm volatile("cp.async.commit_group;")
#define CP_WAIT1()   asm volatile("cp.async.wait_group 1;")
#define CP_WAIT0()   asm volatile("cp.async.wait_group 0;")

__device__ __forceinline__ void mma16816(float* d, const uint32_t* a, uint32_t b0, uint32_t b1)
{
    asm volatile(
        "mma.sync.aligned.m16n8k16.row.col.f32.bf16.bf16.f32 "
        "{%0,%1,%2,%3}, {%4,%5,%6,%7}, {%8,%9}, {%0,%1,%2,%3};"
        : "+f"(d[0]), "+f"(d[1]), "+f"(d[2]), "+f"(d[3])
        : "r"(a[0]), "r"(a[1]), "r"(a[2]), "r"(a[3]), "r"(b0), "r"(b1));
}

__device__ __forceinline__ void split_pack(float a, float b, uint32_t& hi, uint32_t& lo)
{
    __nv_bfloat16 ha = __float2bfloat16(a), hb = __float2bfloat16(b);
    __nv_bfloat16 la = __float2bfloat16(a - __bfloat162float(ha));
    __nv_bfloat16 lb = __float2bfloat16(b - __bfloat162float(hb));
    hi = ((uint32_t)__bfloat16_as_ushort(hb) << 16) | __bfloat16_as_ushort(ha);
    lo = ((uint32_t)__bfloat16_as_ushort(lb) << 16) | __bfloat16_as_ushort(la);
}

// ---------------------------------------------------------------------------
// Prep kernels
// ---------------------------------------------------------------------------
__global__ __launch_bounds__(256)
void split_f32(const float* __restrict__ in, __nv_bfloat16* __restrict__ hi,
               __nv_bfloat16* __restrict__ lo, int n)
{
    int i = (blockIdx.x * blockDim.x + threadIdx.x) * 4;
    if (i >= n) return;
    float4 v = *reinterpret_cast<const float4*>(in + i);
    uint32_t h0, l0, h1, l1;
    split_pack(v.x, v.y, h0, l0);
    split_pack(v.z, v.w, h1, l1);
    reinterpret_cast<uint32_t*>(hi + i)[0] = h0;
    reinterpret_cast<uint32_t*>(hi + i)[1] = h1;
    reinterpret_cast<uint32_t*>(lo + i)[0] = l0;
    reinterpret_cast<uint32_t*>(lo + i)[1] = l1;
}

// W[K,N] fp32 -> T[N,K] bf16 hi/lo
__global__ __launch_bounds__(256)
void transpose_split(const float* __restrict__ W, __nv_bfloat16* __restrict__ Th,
                     __nv_bfloat16* __restrict__ Tl, int K, int N)
{
    __shared__ float tile[32][33];
    const int n0 = blockIdx.x * 32;
    const int k0 = blockIdx.y * 32;
    const int tx = threadIdx.x;
    const int ty = threadIdx.y;
    #pragma unroll
    for (int r = ty; r < 32; r += 8)
        tile[r][tx] = W[(size_t)(k0 + r) * N + n0 + tx];
    __syncthreads();
    #pragma unroll
    for (int r = ty; r < 32; r += 8) {
        float a = tile[tx][r];
        __nv_bfloat16 h = __float2bfloat16(a);
        __nv_bfloat16 l = __float2bfloat16(a - __bfloat162float(h));
        size_t o = (size_t)(n0 + r) * K + k0 + tx;
        Th[o] = h;
        Tl[o] = l;
    }
}

// Q/K sections of g_qkv -> per-head bf16 hi/lo (Q scaled by ATTN_SCALE)
__global__ __launch_bounds__(256)
void split_qk()
{
    int idx = blockIdx.x * 256 + threadIdx.x;
    int e   = idx * 4;
    int row = e / 2560;
    int col = e % 2560;
    if (row >= MM) return;
    int b = row >> 11, s = row & 2047;
    float4 v = *reinterpret_cast<const float4*>(&g_qkv[(size_t)row * QKV_OUT + col]);
    __nv_bfloat16 *dh, *dl;
    if (col < 2048) {
        int hq = col >> 6, d = col & 63;
        size_t o = ((size_t)(b * NHQ + hq) * SS + s) * DK + d;
        dh = g_qh + o; dl = g_ql + o;
        v.x *= ATTN_SCALE; v.y *= ATTN_SCALE; v.z *= ATTN_SCALE; v.w *= ATTN_SCALE;
    } else {
        int cc = col - 2048;
        int n = cc >> 6, d = cc & 63;
        size_t o = ((size_t)(b * NHKV + n) * SS + s) * DK + d;
        dh = g_kh + o; dl = g_kl + o;
    }
    uint32_t h0, l0, h1, l1;
    split_pack(v.x, v.y, h0, l0);
    split_pack(v.z, v.w, h1, l1);
    reinterpret_cast<uint32_t*>(dh)[0] = h0;
    reinterpret_cast<uint32_t*>(dh)[1] = h1;
    reinterpret_cast<uint32_t*>(dl)[0] = l0;
    reinterpret_cast<uint32_t*>(dl)[1] = l1;
}

// V section of g_qkv -> transposed [b][n][d][s] bf16 hi/lo
__global__ __launch_bounds__(256)
void transpose_split_v()
{
    __shared__ float tile[32][33];
    const int s0 = blockIdx.x * 32;
    const int d0 = blockIdx.y * 32;
    const int bz = blockIdx.z;
    const int b  = bz >> 3, n = bz & 7;
    const int tx = threadIdx.x;
    const int ty = threadIdx.y;
    const int colbase = 2560 + n * 64 + d0;
    #pragma unroll
    for (int r = ty; r < 32; r += 8)
        tile[r][tx] = g_qkv[(size_t)(b * SS + s0 + r) * QKV_OUT + colbase + tx];
    __syncthreads();
    #pragma unroll
    for (int r = ty; r < 32; r += 8) {
        float a = tile[tx][r];
        __nv_bfloat16 h = __float2bfloat16(a);
        __nv_bfloat16 l = __float2bfloat16(a - __bfloat162float(h));
        size_t o = ((size_t)(b * NHKV + n) * DV + d0 + r) * SS + s0 + tx;
        g_vth[o] = h;
        g_vtl[o] = l;
    }
}

// ---------------------------------------------------------------------------
// HMMA split GEMM, cp.async double-buffered, 64x64 warp tiles.
// CTA 128x128, K-chunk 32, 4 warps (2x2), 2 CTAs/SM.
// ---------------------------------------------------------------------------
#define SPAD 40
#define TILE_ELEMS (128 * SPAD)
#define TILE_BYTES (TILE_ELEMS * 2)       // 10240
#define GSMEM_BYTES (TILE_BYTES * 8)      // 81920

__global__ __launch_bounds__(128, 2)
void gemm_hmma(const __nv_bfloat16* __restrict__ Ah, const __nv_bfloat16* __restrict__ Al,
               const __nv_bfloat16* __restrict__ Bh, const __nv_bfloat16* __restrict__ Bl,
               float* __restrict__ C, const float* __restrict__ bias,
               int M, int N, int K, int hasBias)
{
    extern __shared__ __nv_bfloat16 dsm[];
    const int tid  = threadIdx.x;
    const int wid  = tid >> 5;
    const int lane = tid & 31;
    const int wm   = (wid >> 1) * 64;     // 0 or 64
    const int wn   = (wid & 1) * 64;      // 0 or 64
    const int bm   = blockIdx.y * 128;
    const int bn   = blockIdx.x * 128;
    const int lrow = lane >> 2;
    const int lkb  = (lane & 3) * 2;
    const uint32_t sb = smem_to_u32(dsm);

    float acc[4][8][4];
    #pragma unroll
    for (int i = 0; i < 4; i++)
        #pragma unroll
        for (int j = 0; j < 8; j++)
            #pragma unroll
            for (int c = 0; c < 4; c++) acc[i][j][c] = 0.0f;

    const int nCh = K >> 5;

    auto issue = [&](int k0, int st) {
        #pragma unroll
        for (int i = 0; i < 4; i++) {
            const int idx = tid + i * 128;
            const int r   = idx >> 2;
            const int c8  = (idx & 3) * 8;
            const size_t gA = (size_t)(bm + r) * K + k0 + c8;
            const size_t gB = (size_t)(bn + r) * K + k0 + c8;
            const uint32_t so = (uint32_t)((r * SPAD + c8) * 2);
            cp_async16(sb + (0 * 2 + st) * TILE_BYTES + so, Ah + gA);
            cp_async16(sb + (1 * 2 + st) * TILE_BYTES + so, Al + gA);
            cp_async16(sb + (2 * 2 + st) * TILE_BYTES + so, Bh + gB);
            cp_async16(sb + (3 * 2 + st) * TILE_BYTES + so, Bl + gB);
        }
        CP_COMMIT();
    };

    issue(0, 0);
    for (int c = 0; c < nCh; c++) {
        if (c + 1 < nCh) { issue((c + 1) << 5, (c + 1) & 1); CP_WAIT1(); }
        else             { CP_WAIT0(); }
        __syncthreads();

        const __nv_bfloat16* sAh = dsm + (0 * 2 + (c & 1)) * TILE_ELEMS;
        const __nv_bfloat16* sAl = dsm + (1 * 2 + (c & 1)) * TILE_ELEMS;
        const __nv_bfloat16* sBh = dsm + (2 * 2 + (c & 1)) * TILE_ELEMS;
        const __nv_bfloat16* sBl = dsm + (3 * 2 + (c & 1)) * TILE_ELEMS;

        #pragma unroll
        for (int ks = 0; ks < 2; ks++) {
            const int kb = ks * 16 + lkb;
            uint32_t ah[4][4], al[4][4];
            #pragma unroll
            for (int mi = 0; mi < 4; mi++) {
                const int r0 = wm + mi * 16 + lrow;
                ah[mi][0] = *reinterpret_cast<const uint32_t*>(&sAh[r0 * SPAD + kb]);
                ah[mi][1] = *reinterpret_cast<const uint32_t*>(&sAh[(r0 + 8) * SPAD + kb]);
                ah[mi][2] = *reinterpret_cast<const uint32_t*>(&sAh[r0 * SPAD + kb + 8]);
                ah[mi][3] = *reinterpret_cast<const uint32_t*>(&sAh[(r0 + 8) * SPAD + kb + 8]);
                al[mi][0] = *reinterpret_cast<const uint32_t*>(&sAl[r0 * SPAD + kb]);
                al[mi][1] = *reinterpret_cast<const uint32_t*>(&sAl[(r0 + 8) * SPAD + kb]);
                al[mi][2] = *reinterpret_cast<const uint32_t*>(&sAl[r0 * SPAD + kb + 8]);
                al[mi][3] = *reinterpret_cast<const uint32_t*>(&sAl[(r0 + 8) * SPAD + kb + 8]);
            }
            #pragma unroll
            for (int ni = 0; ni < 8; ni++) {
                const int n0 = wn + ni * 8 + lrow;
                uint32_t bh0 = *reinterpret_cast<const uint32_t*>(&sBh[n0 * SPAD + kb]);
                uint32_t bh1 = *reinterpret_cast<const uint32_t*>(&sBh[n0 * SPAD + kb + 8]);
                uint32_t bl0 = *reinterpret_cast<const uint32_t*>(&sBl[n0 * SPAD + kb]);
                uint32_t bl1 = *reinterpret_cast<const uint32_t*>(&sBl[n0 * SPAD + kb + 8]);
                #pragma unroll
                for (int mi = 0; mi < 4; mi++) {
                    mma16816(acc[mi][ni], ah[mi], bh0, bh1);
                    mma16816(acc[mi][ni], ah[mi], bl0, bl1);
                    mma16816(acc[mi][ni], al[mi], bh0, bh1);
                }
            }
        }
        __syncthreads();
    }

    #pragma unroll
    for (int mi = 0; mi < 4; mi++) {
        const int r0 = bm + wm + mi * 16 + lrow;
        #pragma unroll
        for (int ni = 0; ni < 8; ni++) {
            const int col = bn + wn + ni * 8 + lkb;
            float b0 = 0.f, b1 = 0.f;
            if (hasBias) { b0 = bias[col]; b1 = bias[col + 1]; }
            float2 v0 = make_float2(acc[mi][ni][0] + b0, acc[mi][ni][1] + b1);
            float2 v1 = make_float2(acc[mi][ni][2] + b0, acc[mi][ni][3] + b1);
            *reinterpret_cast<float2*>(&C[(size_t)r0 * N + col])       = v0;
            *reinterpret_cast<float2*>(&C[(size_t)(r0 + 8) * N + col]) = v1;
        }
    }
}

// ---------------------------------------------------------------------------
// Tensor-core causal flash attention (GQA) — unchanged from R7
// ---------------------------------------------------------------------------
#define APAD 72

__global__ __launch_bounds__(128)
void attn_tc()
{
    __shared__ __nv_bfloat16 sKh[64][APAD];
    __shared__ __nv_bfloat16 sKl[64][APAD];
    __shared__ __nv_bfloat16 sVh[64][APAD];
    __shared__ __nv_bfloat16 sVl[64][APAD];

    const int tid  = threadIdx.x;
    const int wid  = tid >> 5;
    const int lane = tid & 31;
    const int g    = lane >> 2;
    const int tig  = lane & 3;
    const int qt   = (int)gridDim.x - 1 - (int)blockIdx.x;
    const int bh   = blockIdx.y;
    const int b    = bh >> 5;
    const int hq   = bh & 31;
    const int n    = hq >> 2;
    const int wm   = wid * 16;

    const __nv_bfloat16* qhb = g_qh + ((size_t)(b * NHQ + hq) * SS + qt * 64) * DK;
    const __nv_bfloat16* qlb = g_ql + ((size_t)(b * NHQ + hq) * SS + qt * 64) * DK;
    #pragma unroll
    for (int it = 0; it < 4; it++) {
        const int idx = it * 128 + tid;
        const int r = idx >> 3, c8 = (idx & 7) * 8;
        *reinterpret_cast<uint4*>(&sKh[r][c8]) = *reinterpret_cast<const uint4*>(qhb + r * DK + c8);
        *reinterpret_cast<uint4*>(&sKl[r][c8]) = *reinterpret_cast<const uint4*>(qlb + r * DK + c8);
    }
    __syncthreads();
    uint32_t qh[4][4], ql[4][4];
    #pragma unroll
    for (int ks = 0; ks < 4; ks++) {
        const int r0 = wm + g;
        const int kb = ks * 16 + tig * 2;
        qh[ks][0] = *reinterpret_cast<const uint32_t*>(&sKh[r0][kb]);
        qh[ks][1] = *reinterpret_cast<const uint32_t*>(&sKh[r0 + 8][kb]);
        qh[ks][2] = *reinterpret_cast<const uint32_t*>(&sKh[r0][kb + 8]);
        qh[ks][3] = *reinterpret_cast<const uint32_t*>(&sKh[r0 + 8][kb + 8]);
        ql[ks][0] = *reinterpret_cast<const uint32_t*>(&sKl[r0][kb]);
        ql[ks][1] = *reinterpret_cast<const uint32_t*>(&sKl[r0 + 8][kb]);
        ql[ks][2] = *reinterpret_cast<const uint32_t*>(&sKl[r0][kb + 8]);
        ql[ks][3] = *reinterpret_cast<const uint32_t*>(&sKl[r0 + 8][kb + 8]);
    }

    float oacc[8][4];
    #pragma unroll
    for (int i = 0; i < 8; i++)
        #pragma unroll
        for (int c = 0; c < 4; c++) oacc[i][c] = 0.0f;
    float m0 = -INFINITY, m1 = -INFINITY, l0 = 0.0f, l1 = 0.0f;

    const __nv_bfloat16* khb = g_kh  + (size_t)(b * NHKV + n) * SS * DK;
    const __nv_bfloat16* klb = g_kl  + (size_t)(b * NHKV + n) * SS * DK;
    const __nv_bfloat16* vhb = g_vth + (size_t)(b * NHKV + n) * DV * SS;
    const __nv_bfloat16* vlb = g_vtl + (size_t)(b * NHKV + n) * DV * SS;

    for (int kt = 0; kt <= qt; kt++) {
        __syncthreads();
        #pragma unroll
        for (int it = 0; it < 4; it++) {
            const int idx = it * 128 + tid;
            const int r = idx >> 3, c8 = (idx & 7) * 8;
            *reinterpret_cast<uint4*>(&sKh[r][c8]) =
                *reinterpret_cast<const uint4*>(khb + (size_t)(kt * 64 + r) * DK + c8);
            *reinterpret_cast<uint4*>(&sKl[r][c8]) =
                *reinterpret_cast<const uint4*>(klb + (size_t)(kt * 64 + r) * DK + c8);
            *reinterpret_cast<uint4*>(&sVh[r][c8]) =
                *reinterpret_cast<const uint4*>(vhb + (size_t)r * SS + kt * 64 + c8);
            *reinterpret_cast<uint4*>(&sVl[r][c8]) =
                *reinterpret_cast<const uint4*>(vlb + (size_t)r * SS + kt * 64 + c8);
        }
        __syncthreads();

        float sacc[8][4];
        #pragma unroll
        for (int i = 0; i < 8; i++)
            #pragma unroll
            for (int c = 0; c < 4; c++) sacc[i][c] = 0.0f;

        #pragma unroll
        for (int ni = 0; ni < 8; ni++) {
            const int kr = ni * 8 + g;
            #pragma unroll
            for (int ks = 0; ks < 4; ks++) {
                const int kb = ks * 16 + tig * 2;
                uint32_t kh0 = *reinterpret_cast<const uint32_t*>(&sKh[kr][kb]);
                uint32_t kh1 = *reinterpret_cast<const uint32_t*>(&sKh[kr][kb + 8]);
                uint32_t kl0 = *reinterpret_cast<const uint32_t*>(&sKl[kr][kb]);
                uint32_t kl1 = *reinterpret_cast<const uint32_t*>(&sKl[kr][kb + 8]);
                mma16816(sacc[ni], qh[ks], kh0, kh1);
                mma16816(sacc[ni], qh[ks], kl0, kl1);
                mma16816(sacc[ni], ql[ks], kh0, kh1);
            }
        }

        if (kt == qt) {
            #pragma unroll
            for (int ni = 0; ni < 8; ni++) {
                #pragma unroll
                for (int c = 0; c < 4; c++) {
                    const int jl = ni * 8 + tig * 2 + (c & 1);
                    const int il = wm + g + ((c & 2) ? 8 : 0);
                    if (jl > il) sacc[ni][c] = -INFINITY;
                }
            }
        }

        float rmax0 = -INFINITY, rmax1 = -INFINITY;
        #pragma unroll
        for (int ni = 0; ni < 8; ni++) {
            rmax0 = fmaxf(rmax0, fmaxf(sacc[ni][0], sacc[ni][1]));
            rmax1 = fmaxf(rmax1, fmaxf(sacc[ni][2], sacc[ni][3]));
        }
        rmax0 = fmaxf(rmax0, __shfl_xor_sync(0xffffffffu, rmax0, 1));
        rmax0 = fmaxf(rmax0, __shfl_xor_sync(0xffffffffu, rmax0, 2));
        rmax1 = fmaxf(rmax1, __shfl_xor_sync(0xffffffffu, rmax1, 1));
        rmax1 = fmaxf(rmax1, __shfl_xor_sync(0xffffffffu, rmax1, 2));

        const float mn0 = fmaxf(m0, rmax0);
        const float mn1 = fmaxf(m1, rmax1);
        const float cr0 = __expf(m0 - mn0);
        const float cr1 = __expf(m1 - mn1);
        float rs0 = 0.0f, rs1 = 0.0f;
        #pragma unroll
        for (int ni = 0; ni < 8; ni++) {
            float p0 = __expf(sacc[ni][0] - mn0);
            float p1 = __expf(sacc[ni][1] - mn0);
            float p2 = __expf(sacc[ni][2] - mn1);
            float p3 = __expf(sacc[ni][3] - mn1);
            sacc[ni][0] = p0; sacc[ni][1] = p1; sacc[ni][2] = p2; sacc[ni][3] = p3;
            rs0 += p0 + p1;
            rs1 += p2 + p3;
        }
        rs0 += __shfl_xor_sync(0xffffffffu, rs0, 1);
        rs0 += __shfl_xor_sync(0xffffffffu, rs0, 2);
        rs1 += __shfl_xor_sync(0xffffffffu, rs1, 1);
        rs1 += __shfl_xor_sync(0xffffffffu, rs1, 2);
        l0 = l0 * cr0 + rs0;
        l1 = l1 * cr1 + rs1;
        m0 = mn0; m1 = mn1;
        #pragma unroll
        for (int ni = 0; ni < 8; ni++) {
            oacc[ni][0] *= cr0; oacc[ni][1] *= cr0;
            oacc[ni][2] *= cr1; oacc[ni][3] *= cr1;
        }

        #pragma unroll
        for (int ks = 0; ks < 4; ks++) {
            uint32_t ph[4], pl[4];
            split_pack(sacc[2 * ks][0],     sacc[2 * ks][1],     ph[0], pl[0]);
            split_pack(sacc[2 * ks][2],     sacc[2 * ks][3],     ph[1], pl[1]);
            split_pack(sacc[2 * ks + 1][0], sacc[2 * ks + 1][1], ph[2], pl[2]);
            split_pack(sacc[2 * ks + 1][2], sacc[2 * ks + 1][3], ph[3], pl[3]);
            #pragma unroll
            for (int ni = 0; ni < 8; ni++) {
                const int vr = ni * 8 + g;
                const int kk = ks * 16 + tig * 2;
                uint32_t vh0 = *reinterpret_cast<const uint32_t*>(&sVh[vr][kk]);
                uint32_t vh1 = *reinterpret_cast<const uint32_t*>(&sVh[vr][kk + 8]);
                uint32_t vl0 = *reinterpret_cast<const uint32_t*>(&sVl[vr][kk]);
                uint32_t vl1 = *reinterpret_cast<const uint32_t*>(&sVl[vr][kk + 8]);
                mma16816(oacc[ni], ph, vh0, vh1);
                mma16816(oacc[ni], ph, vl0, vl1);
                mma16816(oacc[ni], pl, vh0, vh1);
            }
        }
    }

    const float inv0 = 1.0f / l0;
    const float inv1 = 1.0f / l1;
    const size_t r0g = (size_t)(b * SS + qt * 64 + wm + g);
    const size_t r1g = r0g + 8;
    #pragma unroll
    for (int ni = 0; ni < 8; ni++) {
        const int col = hq * DV + ni * 8 + tig * 2;
        uint32_t hi, lo;
        split_pack(oacc[ni][0] * inv0, oacc[ni][1] * inv0, hi, lo);
        *reinterpret_cast<uint32_t*>(&g_ah[r0g * HH + col]) = hi;
        *reinterpret_cast<uint32_t*>(&g_al[r0g * HH + col]) = lo;
        split_pack(oacc[ni][2] * inv1, oacc[ni][3] * inv1, hi, lo);
        *reinterpret_cast<uint32_t*>(&g_ah[r1g * HH + col]) = hi;
        *reinterpret_cast<uint32_t*>(&g_al[r1g * HH + col]) = lo;
    }
}

// ---------------------------------------------------------------------------
// Launcher
// ---------------------------------------------------------------------------
extern "C" void kernel_launch(void* const* d_in, const int* in_sizes, int n_in,
                              void* d_out, int out_size)
{
    const float* x     = (const float*)d_in[0];
    const float* Wqkv  = (const float*)d_in[1];
    const float* Wout  = (const float*)d_in[2];
    const float* b_out = (const float*)d_in[3];
    float* out = (float*)d_out;

    float* qkv_p;
    __nv_bfloat16 *ah_p, *al_p, *wqh_p, *wql_p, *woh_p, *wol_p;
    cudaGetSymbolAddress((void**)&qkv_p, g_qkv);
    cudaGetSymbolAddress((void**)&ah_p,  g_ah);
    cudaGetSymbolAddress((void**)&al_p,  g_al);
    cudaGetSymbolAddress((void**)&wqh_p, g_wqh);
    cudaGetSymbolAddress((void**)&wql_p, g_wql);
    cudaGetSymbolAddress((void**)&woh_p, g_woh);
    cudaGetSymbolAddress((void**)&wol_p, g_wol);

    cudaFuncSetAttribute(gemm_hmma, cudaFuncAttributeMaxDynamicSharedMemorySize,
                         GSMEM_BYTES);

    // Prep: split x; transpose+split weights
    {
        const int n = MM * HH;
        split_f32<<<n / (256 * 4), 256>>>(x, ah_p, al_p, n);
    }
    transpose_split<<<dim3(QKV_OUT / 32, HH / 32), dim3(32, 8)>>>(Wqkv, wqh_p, wql_p, HH, QKV_OUT);
    transpose_split<<<dim3(HH / 32, HH / 32), dim3(32, 8)>>>(Wout, woh_p, wol_p, HH, HH);

    // 1) QKV projection
    gemm_hmma<<<dim3(QKV_OUT / 128, MM / 128), 128, GSMEM_BYTES>>>(
        ah_p, al_p, wqh_p, wql_p, qkv_p, nullptr, MM, QKV_OUT, HH, 0);

    // 2) Split Q/K (scaled) and transpose-split V
    split_qk<<<(MM * 2560 / 4) / 256, 256>>>();
    transpose_split_v<<<dim3(SS / 32, DV / 32, BB * NHKV), dim3(32, 8)>>>();

    // 3) Tensor-core flash attention -> writes g_ah/g_al
    attn_tc<<<dim3(SS / 64, BB * NHQ), 128>>>();

    // 4) Output projection + bias
    gemm_hmma<<<dim3(HH / 128, MM / 128), 128, GSMEM_BYTES>>>(
        ah_p, al_p, woh_p, wol_p, out, b_out, MM, HH, HH, 1);
}

// round 10
// speedup vs baseline: 4.2824x; 1.3802x over previous
#include <cuda_runtime.h>
#include <cuda_fp16.h>
#include <math.h>
#include <stdint.h>

#define BB   2
#define SS   2048
#define HH   2048
#define NHQ  32
#define NHKV 8
#define DK   64
#define DV   64
#define QKV_OUT 3072
#define ATTN_SCALE 0.125f
#define MM   (BB * SS)  // 4096

// ---------------------------------------------------------------------------
// Scratch (device globals)
// ---------------------------------------------------------------------------
__device__ float  g_qkv [BB * SS * QKV_OUT];        // fp32 QKV
__device__ __half g_ah[MM * HH];                    // A hi (x, then attn-out)
__device__ __half g_al[MM * HH];                    // A lo
__device__ __half g_wqh[QKV_OUT * HH];              // Wqkv^T hi [N,K]
__device__ __half g_woh[HH * HH];                   // Wout^T hi [N,K]
// attention operands (fp16)
__device__ __half g_qh [BB * NHQ  * SS * DK];       // scaled Q hi
__device__ __half g_ql [BB * NHQ  * SS * DK];       // scaled Q lo
__device__ __half g_kh [BB * NHKV * SS * DK];       // K hi
__device__ __half g_vth[BB * NHKV * DV * SS];       // V^T hi [b][n][d][s]

// ---------------------------------------------------------------------------
// Helpers
// ---------------------------------------------------------------------------
__device__ __forceinline__ uint32_t smem_to_u32(const void* p) {
    uint32_t a;
    asm("{ .reg .u64 t; cvta.to.shared.u64 t, %1; cvt.u32.u64 %0, t; }" : "=r"(a) : "l"(p));
    return a;
}
__device__ __forceinline__ void cp_async16(uint32_t dst, const void* src) {
    asm volatile("cp.async.cg.shared.global [%0], [%1], 16;" :: "r"(dst), "l"(src));
}
#define CP_COMMIT()  asm volatile("cp.async.commit_group;")
#define CP_WAIT1()   asm volatile("cp.async.wait_group 1;")
#define CP_WAIT0()   asm volatile("cp.async.wait_group 0;")

__device__ __forceinline__ void mma16816(float* d, const uint32_t* a, uint32_t b0, uint32_t b1)
{
    asm volatile(
        "mma.sync.aligned.m16n8k16.row.col.f32.f16.f16.f32 "
        "{%0,%1,%2,%3}, {%4,%5,%6,%7}, {%8,%9}, {%0,%1,%2,%3};"
        : "+f"(d[0]), "+f"(d[1]), "+f"(d[2]), "+f"(d[3])
        : "r"(a[0]), "r"(a[1]), "r"(a[2]), "r"(a[3]), "r"(b0), "r"(b1));
}

// fp32 pair -> packed fp16 hi + packed fp16 lo (residual)
__device__ __forceinline__ void split_pack(float a, float b, uint32_t& hi, uint32_t& lo)
{
    __half ha = __float2half_rn(a), hb = __float2half_rn(b);
    __half la = __float2half_rn(a - __half2float(ha));
    __half lb = __float2half_rn(b - __half2float(hb));
    hi = ((uint32_t)__half_as_ushort(hb) << 16) | __half_as_ushort(ha);
    lo = ((uint32_t)__half_as_ushort(lb) << 16) | __half_as_ushort(la);
}

// ---------------------------------------------------------------------------
// Prep kernels
// ---------------------------------------------------------------------------
__global__ __launch_bounds__(256)
void split_f32(const float* __restrict__ in, __half* __restrict__ hi,
               __half* __restrict__ lo, int n)
{
    int i = (blockIdx.x * blockDim.x + threadIdx.x) * 4;
    if (i >= n) return;
    float4 v = *reinterpret_cast<const float4*>(in + i);
    uint32_t h0, l0, h1, l1;
    split_pack(v.x, v.y, h0, l0);
    split_pack(v.z, v.w, h1, l1);
    reinterpret_cast<uint32_t*>(hi + i)[0] = h0;
    reinterpret_cast<uint32_t*>(hi + i)[1] = h1;
    reinterpret_cast<uint32_t*>(lo + i)[0] = l0;
    reinterpret_cast<uint32_t*>(lo + i)[1] = l1;
}

// W[K,N] fp32 -> T[N,K] fp16 hi only
__global__ __launch_bounds__(256)
void transpose_h(const float* __restrict__ W, __half* __restrict__ Th, int K, int N)
{
    __shared__ float tile[32][33];
    const int n0 = blockIdx.x * 32;
    const int k0 = blockIdx.y * 32;
    const int tx = threadIdx.x;
    const int ty = threadIdx.y;
    #pragma unroll
    for (int r = ty; r < 32; r += 8)
        tile[r][tx] = W[(size_t)(k0 + r) * N + n0 + tx];
    __syncthreads();
    #pragma unroll
    for (int r = ty; r < 32; r += 8)
        Th[(size_t)(n0 + r) * K + k0 + tx] = __float2half_rn(tile[tx][r]);
}

// Q/K sections of g_qkv -> per-head fp16 (Q hi/lo scaled; K hi only)
__global__ __launch_bounds__(256)
void split_qk()
{
    int idx = blockIdx.x * 256 + threadIdx.x;
    int e   = idx * 4;
    int row = e / 2560;
    int col = e % 2560;
    if (row >= MM) return;
    int b = row >> 11, s = row & 2047;
    float4 v = *reinterpret_cast<const float4*>(&g_qkv[(size_t)row * QKV_OUT + col]);
    if (col < 2048) {
        int hq = col >> 6, d = col & 63;
        size_t o = ((size_t)(b * NHQ + hq) * SS + s) * DK + d;
        v.x *= ATTN_SCALE; v.y *= ATTN_SCALE; v.z *= ATTN_SCALE; v.w *= ATTN_SCALE;
        uint32_t h0, l0, h1, l1;
        split_pack(v.x, v.y, h0, l0);
        split_pack(v.z, v.w, h1, l1);
        reinterpret_cast<uint32_t*>(g_qh + o)[0] = h0;
        reinterpret_cast<uint32_t*>(g_qh + o)[1] = h1;
        reinterpret_cast<uint32_t*>(g_ql + o)[0] = l0;
        reinterpret_cast<uint32_t*>(g_ql + o)[1] = l1;
    } else {
        int cc = col - 2048;
        int n = cc >> 6, d = cc & 63;
        size_t o = ((size_t)(b * NHKV + n) * SS + s) * DK + d;
        uint32_t h0 = ((uint32_t)__half_as_ushort(__float2half_rn(v.y)) << 16)
                    | __half_as_ushort(__float2half_rn(v.x));
        uint32_t h1 = ((uint32_t)__half_as_ushort(__float2half_rn(v.w)) << 16)
                    | __half_as_ushort(__float2half_rn(v.z));
        reinterpret_cast<uint32_t*>(g_kh + o)[0] = h0;
        reinterpret_cast<uint32_t*>(g_kh + o)[1] = h1;
    }
}

// V section of g_qkv -> transposed [b][n][d][s] fp16 hi only
__global__ __launch_bounds__(256)
void transpose_v()
{
    __shared__ float tile[32][33];
    const int s0 = blockIdx.x * 32;
    const int d0 = blockIdx.y * 32;
    const int bz = blockIdx.z;
    const int b  = bz >> 3, n = bz & 7;
    const int tx = threadIdx.x;
    const int ty = threadIdx.y;
    const int colbase = 2560 + n * 64 + d0;
    #pragma unroll
    for (int r = ty; r < 32; r += 8)
        tile[r][tx] = g_qkv[(size_t)(b * SS + s0 + r) * QKV_OUT + colbase + tx];
    __syncthreads();
    #pragma unroll
    for (int r = ty; r < 32; r += 8) {
        size_t o = ((size_t)(b * NHKV + n) * DV + d0 + r) * SS + s0 + tx;
        g_vth[o] = __float2half_rn(tile[tx][r]);
    }
}

// ---------------------------------------------------------------------------
// HMMA fp16 2-product GEMM: C = (Ah + Al) @ Bh^T (+bias), Bt [N,K] K-major.
// CTA 128x128, K-chunk 32, 4 warps (64x64 warp tiles), 2 stages, 2 CTAs/SM.
// ---------------------------------------------------------------------------
#define SPAD 40
#define TILE_ELEMS (128 * SPAD)
#define TILE_BYTES (TILE_ELEMS * 2)       // 10240
#define GSMEM_BYTES (TILE_BYTES * 6)      // 3 tiles x 2 stages = 61440

__global__ __launch_bounds__(128, 2)
void gemm_hmma(const __half* __restrict__ Ah, const __half* __restrict__ Al,
               const __half* __restrict__ Bh,
               float* __restrict__ C, const float* __restrict__ bias,
               int M, int N, int K, int hasBias)
{
    extern __shared__ __half dsm[];
    const int tid  = threadIdx.x;
    const int wid  = tid >> 5;
    const int lane = tid & 31;
    const int wm   = (wid >> 1) * 64;
    const int wn   = (wid & 1) * 64;
    const int bm   = blockIdx.y * 128;
    const int bn   = blockIdx.x * 128;
    const int lrow = lane >> 2;
    const int lkb  = (lane & 3) * 2;
    const uint32_t sb = smem_to_u32(dsm);

    float acc[4][8][4];
    #pragma unroll
    for (int i = 0; i < 4; i++)
        #pragma unroll
        for (int j = 0; j < 8; j++)
            #pragma unroll
            for (int c = 0; c < 4; c++) acc[i][j][c] = 0.0f;

    const int nCh = K >> 5;

    auto issue = [&](int k0, int st) {
        #pragma unroll
        for (int i = 0; i < 4; i++) {
            const int idx = tid + i * 128;
            const int r   = idx >> 2;
            const int c8  = (idx & 3) * 8;
            const size_t gA = (size_t)(bm + r) * K + k0 + c8;
            const size_t gB = (size_t)(bn + r) * K + k0 + c8;
            const uint32_t so = (uint32_t)((r * SPAD + c8) * 2);
            cp_async16(sb + (0 * 2 + st) * TILE_BYTES + so, Ah + gA);
            cp_async16(sb + (1 * 2 + st) * TILE_BYTES + so, Al + gA);
            cp_async16(sb + (2 * 2 + st) * TILE_BYTES + so, Bh + gB);
        }
        CP_COMMIT();
    };

    issue(0, 0);
    for (int c = 0; c < nCh; c++) {
        if (c + 1 < nCh) { issue((c + 1) << 5, (c + 1) & 1); CP_WAIT1(); }
        else             { CP_WAIT0(); }
        __syncthreads();

        const __half* sAh = dsm + (0 * 2 + (c & 1)) * TILE_ELEMS;
        const __half* sAl = dsm + (1 * 2 + (c & 1)) * TILE_ELEMS;
        const __half* sBh = dsm + (2 * 2 + (c & 1)) * TILE_ELEMS;

        #pragma unroll
        for (int ks = 0; ks < 2; ks++) {
            const int kb = ks * 16 + lkb;
            uint32_t ah[4][4], al[4][4];
            #pragma unroll
            for (int mi = 0; mi < 4; mi++) {
                const int r0 = wm + mi * 16 + lrow;
                ah[mi][0] = *reinterpret_cast<const uint32_t*>(&sAh[r0 * SPAD + kb]);
                ah[mi][1] = *reinterpret_cast<const uint32_t*>(&sAh[(r0 + 8) * SPAD + kb]);
                ah[mi][2] = *reinterpret_cast<const uint32_t*>(&sAh[r0 * SPAD + kb + 8]);
                ah[mi][3] = *reinterpret_cast<const uint32_t*>(&sAh[(r0 + 8) * SPAD + kb + 8]);
                al[mi][0] = *reinterpret_cast<const uint32_t*>(&sAl[r0 * SPAD + kb]);
                al[mi][1] = *reinterpret_cast<const uint32_t*>(&sAl[(r0 + 8) * SPAD + kb]);
                al[mi][2] = *reinterpret_cast<const uint32_t*>(&sAl[r0 * SPAD + kb + 8]);
                al[mi][3] = *reinterpret_cast<const uint32_t*>(&sAl[(r0 + 8) * SPAD + kb + 8]);
            }
            #pragma unroll
            for (int ni = 0; ni < 8; ni++) {
                const int n0 = wn + ni * 8 + lrow;
                uint32_t bh0 = *reinterpret_cast<const uint32_t*>(&sBh[n0 * SPAD + kb]);
                uint32_t bh1 = *reinterpret_cast<const uint32_t*>(&sBh[n0 * SPAD + kb + 8]);
                #pragma unroll
                for (int mi = 0; mi < 4; mi++) {
                    mma16816(acc[mi][ni], ah[mi], bh0, bh1);
                    mma16816(acc[mi][ni], al[mi], bh0, bh1);
                }
            }
        }
        __syncthreads();
    }

    #pragma unroll
    for (int mi = 0; mi < 4; mi++) {
        const int r0 = bm + wm + mi * 16 + lrow;
        #pragma unroll
        for (int ni = 0; ni < 8; ni++) {
            const int col = bn + wn + ni * 8 + lkb;
            float b0 = 0.f, b1 = 0.f;
            if (hasBias) { b0 = bias[col]; b1 = bias[col + 1]; }
            float2 v0 = make_float2(acc[mi][ni][0] + b0, acc[mi][ni][1] + b1);
            float2 v1 = make_float2(acc[mi][ni][2] + b0, acc[mi][ni][3] + b1);
            *reinterpret_cast<float2*>(&C[(size_t)r0 * N + col])       = v0;
            *reinterpret_cast<float2*>(&C[(size_t)(r0 + 8) * N + col]) = v1;
        }
    }
}

// ---------------------------------------------------------------------------
// Tensor-core causal flash attention (GQA), fp16 2-product.
// S = Qh K^T + Ql K^T ; O = Ph V + Pl V. 128 threads, 64-query tile.
// Writes O split hi/lo (fp16) directly into g_ah/g_al for gemm2.
// ---------------------------------------------------------------------------
#define APAD 72

__global__ __launch_bounds__(128)
void attn_tc()
{
    __shared__ __half sKh[64][APAD];   // K hi tile (Q hi during prologue)
    __shared__ __half sVh[64][APAD];   // V^T hi tile (Q lo during prologue)

    const int tid  = threadIdx.x;
    const int wid  = tid >> 5;
    const int lane = tid & 31;
    const int g    = lane >> 2;
    const int tig  = lane & 3;
    const int qt   = (int)gridDim.x - 1 - (int)blockIdx.x;
    const int bh   = blockIdx.y;
    const int b    = bh >> 5;
    const int hq   = bh & 31;
    const int n    = hq >> 2;
    const int wm   = wid * 16;

    // --- stage Q hi/lo through smem, pull fragments ---
    const __half* qhb = g_qh + ((size_t)(b * NHQ + hq) * SS + qt * 64) * DK;
    const __half* qlb = g_ql + ((size_t)(b * NHQ + hq) * SS + qt * 64) * DK;
    #pragma unroll
    for (int it = 0; it < 4; it++) {
        const int idx = it * 128 + tid;
        const int r = idx >> 3, c8 = (idx & 7) * 8;
        *reinterpret_cast<uint4*>(&sKh[r][c8]) = *reinterpret_cast<const uint4*>(qhb + r * DK + c8);
        *reinterpret_cast<uint4*>(&sVh[r][c8]) = *reinterpret_cast<const uint4*>(qlb + r * DK + c8);
    }
    __syncthreads();
    uint32_t qh[4][4], ql[4][4];
    #pragma unroll
    for (int ks = 0; ks < 4; ks++) {
        const int r0 = wm + g;
        const int kb = ks * 16 + tig * 2;
        qh[ks][0] = *reinterpret_cast<const uint32_t*>(&sKh[r0][kb]);
        qh[ks][1] = *reinterpret_cast<const uint32_t*>(&sKh[r0 + 8][kb]);
        qh[ks][2] = *reinterpret_cast<const uint32_t*>(&sKh[r0][kb + 8]);
        qh[ks][3] = *reinterpret_cast<const uint32_t*>(&sKh[r0 + 8][kb + 8]);
        ql[ks][0] = *reinterpret_cast<const uint32_t*>(&sVh[r0][kb]);
        ql[ks][1] = *reinterpret_cast<const uint32_t*>(&sVh[r0 + 8][kb]);
        ql[ks][2] = *reinterpret_cast<const uint32_t*>(&sVh[r0][kb + 8]);
        ql[ks][3] = *reinterpret_cast<const uint32_t*>(&sVh[r0 + 8][kb + 8]);
    }

    float oacc[8][4];
    #pragma unroll
    for (int i = 0; i < 8; i++)
        #pragma unroll
        for (int c = 0; c < 4; c++) oacc[i][c] = 0.0f;
    float m0 = -INFINITY, m1 = -INFINITY, l0 = 0.0f, l1 = 0.0f;

    const __half* khb = g_kh  + (size_t)(b * NHKV + n) * SS * DK;
    const __half* vhb = g_vth + (size_t)(b * NHKV + n) * DV * SS;

    for (int kt = 0; kt <= qt; kt++) {
        __syncthreads();
        #pragma unroll
        for (int it = 0; it < 4; it++) {
            const int idx = it * 128 + tid;
            const int r = idx >> 3, c8 = (idx & 7) * 8;
            *reinterpret_cast<uint4*>(&sKh[r][c8]) =
                *reinterpret_cast<const uint4*>(khb + (size_t)(kt * 64 + r) * DK + c8);
            *reinterpret_cast<uint4*>(&sVh[r][c8]) =
                *reinterpret_cast<const uint4*>(vhb + (size_t)r * SS + kt * 64 + c8);
        }
        __syncthreads();

        // ---- S = (Qh + Ql) K^T ----
        float sacc[8][4];
        #pragma unroll
        for (int i = 0; i < 8; i++)
            #pragma unroll
            for (int c = 0; c < 4; c++) sacc[i][c] = 0.0f;

        #pragma unroll
        for (int ni = 0; ni < 8; ni++) {
            const int kr = ni * 8 + g;
            #pragma unroll
            for (int ks = 0; ks < 4; ks++) {
                const int kb = ks * 16 + tig * 2;
                uint32_t kh0 = *reinterpret_cast<const uint32_t*>(&sKh[kr][kb]);
                uint32_t kh1 = *reinterpret_cast<const uint32_t*>(&sKh[kr][kb + 8]);
                mma16816(sacc[ni], qh[ks], kh0, kh1);
                mma16816(sacc[ni], ql[ks], kh0, kh1);
            }
        }

        if (kt == qt) {
            #pragma unroll
            for (int ni = 0; ni < 8; ni++) {
                #pragma unroll
                for (int c = 0; c < 4; c++) {
                    const int jl = ni * 8 + tig * 2 + (c & 1);
                    const int il = wm + g + ((c & 2) ? 8 : 0);
                    if (jl > il) sacc[ni][c] = -INFINITY;
                }
            }
        }

        // ---- online softmax ----
        float rmax0 = -INFINITY, rmax1 = -INFINITY;
        #pragma unroll
        for (int ni = 0; ni < 8; ni++) {
            rmax0 = fmaxf(rmax0, fmaxf(sacc[ni][0], sacc[ni][1]));
            rmax1 = fmaxf(rmax1, fmaxf(sacc[ni][2], sacc[ni][3]));
        }
        rmax0 = fmaxf(rmax0, __shfl_xor_sync(0xffffffffu, rmax0, 1));
        rmax0 = fmaxf(rmax0, __shfl_xor_sync(0xffffffffu, rmax0, 2));
        rmax1 = fmaxf(rmax1, __shfl_xor_sync(0xffffffffu, rmax1, 1));
        rmax1 = fmaxf(rmax1, __shfl_xor_sync(0xffffffffu, rmax1, 2));

        const float mn0 = fmaxf(m0, rmax0);
        const float mn1 = fmaxf(m1, rmax1);
        const float cr0 = __expf(m0 - mn0);
        const float cr1 = __expf(m1 - mn1);
        float rs0 = 0.0f, rs1 = 0.0f;
        #pragma unroll
        for (int ni = 0; ni < 8; ni++) {
            float p0 = __expf(sacc[ni][0] - mn0);
            float p1 = __expf(sacc[ni][1] - mn0);
            float p2 = __expf(sacc[ni][2] - mn1);
            float p3 = __expf(sacc[ni][3] - mn1);
            sacc[ni][0] = p0; sacc[ni][1] = p1; sacc[ni][2] = p2; sacc[ni][3] = p3;
            rs0 += p0 + p1;
            rs1 += p2 + p3;
        }
        rs0 += __shfl_xor_sync(0xffffffffu, rs0, 1);
        rs0 += __shfl_xor_sync(0xffffffffu, rs0, 2);
        rs1 += __shfl_xor_sync(0xffffffffu, rs1, 1);
        rs1 += __shfl_xor_sync(0xffffffffu, rs1, 2);
        l0 = l0 * cr0 + rs0;
        l1 = l1 * cr1 + rs1;
        m0 = mn0; m1 = mn1;
        #pragma unroll
        for (int ni = 0; ni < 8; ni++) {
            oacc[ni][0] *= cr0; oacc[ni][1] *= cr0;
            oacc[ni][2] *= cr1; oacc[ni][3] *= cr1;
        }

        // ---- O += (Ph + Pl) V ----
        #pragma unroll
        for (int ks = 0; ks < 4; ks++) {
            uint32_t ph[4], pl[4];
            split_pack(sacc[2 * ks][0],     sacc[2 * ks][1],     ph[0], pl[0]);
            split_pack(sacc[2 * ks][2],     sacc[2 * ks][3],     ph[1], pl[1]);
            split_pack(sacc[2 * ks + 1][0], sacc[2 * ks + 1][1], ph[2], pl[2]);
            split_pack(sacc[2 * ks + 1][2], sacc[2 * ks + 1][3], ph[3], pl[3]);
            #pragma unroll
            for (int ni = 0; ni < 8; ni++) {
                const int vr = ni * 8 + g;
                const int kk = ks * 16 + tig * 2;
                uint32_t vh0 = *reinterpret_cast<const uint32_t*>(&sVh[vr][kk]);
                uint32_t vh1 = *reinterpret_cast<const uint32_t*>(&sVh[vr][kk + 8]);
                mma16816(oacc[ni], ph, vh0, vh1);
                mma16816(oacc[ni], pl, vh0, vh1);
            }
        }
    }

    // ---- epilogue: normalize + split hi/lo into gemm2 A buffers ----
    const float inv0 = 1.0f / l0;
    const float inv1 = 1.0f / l1;
    const size_t r0g = (size_t)(b * SS + qt * 64 + wm + g);
    const size_t r1g = r0g + 8;
    #pragma unroll
    for (int ni = 0; ni < 8; ni++) {
        const int col = hq * DV + ni * 8 + tig * 2;
        uint32_t hi, lo;
        split_pack(oacc[ni][0] * inv0, oacc[ni][1] * inv0, hi, lo);
        *reinterpret_cast<uint32_t*>(&g_ah[r0g * HH + col]) = hi;
        *reinterpret_cast<uint32_t*>(&g_al[r0g * HH + col]) = lo;
        split_pack(oacc[ni][2] * inv1, oacc[ni][3] * inv1, hi, lo);
        *reinterpret_cast<uint32_t*>(&g_ah[r1g * HH + col]) = hi;
        *reinterpret_cast<uint32_t*>(&g_al[r1g * HH + col]) = lo;
    }
}

// ---------------------------------------------------------------------------
// Launcher
// ---------------------------------------------------------------------------
extern "C" void kernel_launch(void* const* d_in, const int* in_sizes, int n_in,
                              void* d_out, int out_size)
{
    const float* x     = (const float*)d_in[0];
    const float* Wqkv  = (const float*)d_in[1];
    const float* Wout  = (const float*)d_in[2];
    const float* b_out = (const float*)d_in[3];
    float* out = (float*)d_out;

    float* qkv_p;
    __half *ah_p, *al_p, *wqh_p, *woh_p;
    cudaGetSymbolAddress((void**)&qkv_p, g_qkv);
    cudaGetSymbolAddress((void**)&ah_p,  g_ah);
    cudaGetSymbolAddress((void**)&al_p,  g_al);
    cudaGetSymbolAddress((void**)&wqh_p, g_wqh);
    cudaGetSymbolAddress((void**)&woh_p, g_woh);

    cudaFuncSetAttribute(gemm_hmma, cudaFuncAttributeMaxDynamicSharedMemorySize,
                         GSMEM_BYTES);

    // Prep: split x (hi/lo); transpose weights (hi only)
    {
        const int n = MM * HH;
        split_f32<<<n / (256 * 4), 256>>>(x, ah_p, al_p, n);
    }
    transpose_h<<<dim3(QKV_OUT / 32, HH / 32), dim3(32, 8)>>>(Wqkv, wqh_p, HH, QKV_OUT);
    transpose_h<<<dim3(HH / 32, HH / 32), dim3(32, 8)>>>(Wout, woh_p, HH, HH);

    // 1) QKV projection
    gemm_hmma<<<dim3(QKV_OUT / 128, MM / 128), 128, GSMEM_BYTES>>>(
        ah_p, al_p, wqh_p, qkv_p, nullptr, MM, QKV_OUT, HH, 0);

    // 2) Split Q (hi/lo, scaled) + K (hi); transpose V (hi)
    split_qk<<<(MM * 2560 / 4) / 256, 256>>>();
    transpose_v<<<dim3(SS / 32, DV / 32, BB * NHKV), dim3(32, 8)>>>();

    // 3) Tensor-core flash attention -> writes g_ah/g_al
    attn_tc<<<dim3(SS / 64, BB * NHQ), 128>>>();

    // 4) Output projection + bias
    gemm_hmma<<<dim3(HH / 128, MM / 128), 128, GSMEM_BYTES>>>(
        ah_p, al_p, woh_p, out, b_out, MM, HH, HH, 1);
}

// round 13
// speedup vs baseline: 4.8794x; 1.1394x over previous
#include <cuda_runtime.h>
#include <cuda_fp16.h>
#include <math.h>
#include <stdint.h>

#define BB   2
#define SS   2048
#define HH   2048
#define NHQ  32
#define NHKV 8
#define DK   64
#define DV   64
#define QKV_OUT 3072
#define ATTN_SCALE 0.125f
#define MM   (BB * SS)  // 4096

// ---------------------------------------------------------------------------
// Scratch (device globals)
// ---------------------------------------------------------------------------
__device__ float  g_qkv [BB * SS * QKV_OUT];        // fp32 QKV
__device__ __half g_ah[MM * HH];                    // A hi (x, then attn-out)
__device__ __half g_al[MM * HH];                    // A lo
__device__ __half g_wqh[QKV_OUT * HH];              // Wqkv^T hi [N,K]
__device__ __half g_woh[HH * HH];                   // Wout^T hi [N,K]
// attention operands (fp16)
__device__ __half g_qh [BB * NHQ  * SS * DK];       // scaled Q hi
__device__ __half g_ql [BB * NHQ  * SS * DK];       // scaled Q lo
__device__ __half g_kh [BB * NHKV * SS * DK];       // K hi
__device__ __half g_vth[BB * NHKV * DV * SS];       // V^T hi [b][n][d][s]

// ---------------------------------------------------------------------------
// Helpers
// ---------------------------------------------------------------------------
__device__ __forceinline__ uint32_t smem_to_u32(const void* p) {
    uint32_t a;
    asm("{ .reg .u64 t; cvta.to.shared.u64 t, %1; cvt.u32.u64 %0, t; }" : "=r"(a) : "l"(p));
    return a;
}
__device__ __forceinline__ void cp_async16(uint32_t dst, const void* src) {
    asm volatile("cp.async.cg.shared.global [%0], [%1], 16;" :: "r"(dst), "l"(src));
}
#define CP_COMMIT()  asm volatile("cp.async.commit_group;")
#define CP_WAIT1()   asm volatile("cp.async.wait_group 1;")
#define CP_WAIT0()   asm volatile("cp.async.wait_group 0;")

#define LDMX4(r, addr) \
    asm volatile("ldmatrix.sync.aligned.m8n8.x4.shared.b16 {%0,%1,%2,%3}, [%4];" \
        : "=r"((r)[0]), "=r"((r)[1]), "=r"((r)[2]), "=r"((r)[3]) : "r"(addr))

__device__ __forceinline__ void mma16816(float* d, const uint32_t* a, uint32_t b0, uint32_t b1)
{
    asm volatile(
        "mma.sync.aligned.m16n8k16.row.col.f32.f16.f16.f32 "
        "{%0,%1,%2,%3}, {%4,%5,%6,%7}, {%8,%9}, {%0,%1,%2,%3};"
        : "+f"(d[0]), "+f"(d[1]), "+f"(d[2]), "+f"(d[3])
        : "r"(a[0]), "r"(a[1]), "r"(a[2]), "r"(a[3]), "r"(b0), "r"(b1));
}

// fp32 pair -> packed fp16 hi + packed fp16 lo (residual)
__device__ __forceinline__ void split_pack(float a, float b, uint32_t& hi, uint32_t& lo)
{
    __half ha = __float2half_rn(a), hb = __float2half_rn(b);
    __half la = __float2half_rn(a - __half2float(ha));
    __half lb = __float2half_rn(b - __half2float(hb));
    hi = ((uint32_t)__half_as_ushort(hb) << 16) | __half_as_ushort(ha);
    lo = ((uint32_t)__half_as_ushort(lb) << 16) | __half_as_ushort(la);
}

// ---------------------------------------------------------------------------
// Prep kernels (unchanged from R10)
// ---------------------------------------------------------------------------
__global__ __launch_bounds__(256)
void split_f32(const float* __restrict__ in, __half* __restrict__ hi,
               __half* __restrict__ lo, int n)
{
    int i = (blockIdx.x * blockDim.x + threadIdx.x) * 4;
    if (i >= n) return;
    float4 v = *reinterpret_cast<const float4*>(in + i);
    uint32_t h0, l0, h1, l1;
    split_pack(v.x, v.y, h0, l0);
    split_pack(v.z, v.w, h1, l1);
    reinterpret_cast<uint32_t*>(hi + i)[0] = h0;
    reinterpret_cast<uint32_t*>(hi + i)[1] = h1;
    reinterpret_cast<uint32_t*>(lo + i)[0] = l0;
    reinterpret_cast<uint32_t*>(lo + i)[1] = l1;
}

__global__ __launch_bounds__(256)
void transpose_h(const float* __restrict__ W, __half* __restrict__ Th, int K, int N)
{
    __shared__ float tile[32][33];
    const int n0 = blockIdx.x * 32;
    const int k0 = blockIdx.y * 32;
    const int tx = threadIdx.x;
    const int ty = threadIdx.y;
    #pragma unroll
    for (int r = ty; r < 32; r += 8)
        tile[r][tx] = W[(size_t)(k0 + r) * N + n0 + tx];
    __syncthreads();
    #pragma unroll
    for (int r = ty; r < 32; r += 8)
        Th[(size_t)(n0 + r) * K + k0 + tx] = __float2half_rn(tile[tx][r]);
}

__global__ __launch_bounds__(256)
void split_qk()
{
    int idx = blockIdx.x * 256 + threadIdx.x;
    int e   = idx * 4;
    int row = e / 2560;
    int col = e % 2560;
    if (row >= MM) return;
    int b = row >> 11, s = row & 2047;
    float4 v = *reinterpret_cast<const float4*>(&g_qkv[(size_t)row * QKV_OUT + col]);
    if (col < 2048) {
        int hq = col >> 6, d = col & 63;
        size_t o = ((size_t)(b * NHQ + hq) * SS + s) * DK + d;
        v.x *= ATTN_SCALE; v.y *= ATTN_SCALE; v.z *= ATTN_SCALE; v.w *= ATTN_SCALE;
        uint32_t h0, l0, h1, l1;
        split_pack(v.x, v.y, h0, l0);
        split_pack(v.z, v.w, h1, l1);
        reinterpret_cast<uint32_t*>(g_qh + o)[0] = h0;
        reinterpret_cast<uint32_t*>(g_qh + o)[1] = h1;
        reinterpret_cast<uint32_t*>(g_ql + o)[0] = l0;
        reinterpret_cast<uint32_t*>(g_ql + o)[1] = l1;
    } else {
        int cc = col - 2048;
        int n = cc >> 6, d = cc & 63;
        size_t o = ((size_t)(b * NHKV + n) * SS + s) * DK + d;
        uint32_t h0 = ((uint32_t)__half_as_ushort(__float2half_rn(v.y)) << 16)
                    | __half_as_ushort(__float2half_rn(v.x));
        uint32_t h1 = ((uint32_t)__half_as_ushort(__float2half_rn(v.w)) << 16)
                    | __half_as_ushort(__float2half_rn(v.z));
        reinterpret_cast<uint32_t*>(g_kh + o)[0] = h0;
        reinterpret_cast<uint32_t*>(g_kh + o)[1] = h1;
    }
}

__global__ __launch_bounds__(256)
void transpose_v()
{
    __shared__ float tile[32][33];
    const int s0 = blockIdx.x * 32;
    const int d0 = blockIdx.y * 32;
    const int bz = blockIdx.z;
    const int b  = bz >> 3, n = bz & 7;
    const int tx = threadIdx.x;
    const int ty = threadIdx.y;
    const int colbase = 2560 + n * 64 + d0;
    #pragma unroll
    for (int r = ty; r < 32; r += 8)
        tile[r][tx] = g_qkv[(size_t)(b * SS + s0 + r) * QKV_OUT + colbase + tx];
    __syncthreads();
    #pragma unroll
    for (int r = ty; r < 32; r += 8) {
        size_t o = ((size_t)(b * NHKV + n) * DV + d0 + r) * SS + s0 + tx;
        g_vth[o] = __float2half_rn(tile[tx][r]);
    }
}

// ---------------------------------------------------------------------------
// HMMA fp16 2-product GEMM with ldmatrix fragment loads.
// CTA 128x128, K-chunk 32, 4 warps (64x64 warp tiles), 2 stages, 2 CTAs/SM.
// ---------------------------------------------------------------------------
#define SPAD 40
#define TILE_ELEMS (128 * SPAD)
#define TILE_BYTES (TILE_ELEMS * 2)       // 10240
#define GSMEM_BYTES (TILE_BYTES * 6)      // 61440

__global__ __launch_bounds__(128, 2)
void gemm_hmma(const __half* __restrict__ Ah, const __half* __restrict__ Al,
               const __half* __restrict__ Bh,
               float* __restrict__ C, const float* __restrict__ bias,
               int M, int N, int K, int hasBias)
{
    extern __shared__ __half dsm[];
    const int tid  = threadIdx.x;
    const int wid  = tid >> 5;
    const int lane = tid & 31;
    const int wm   = (wid >> 1) * 64;
    const int wn   = (wid & 1) * 64;
    const int bm   = blockIdx.y * 128;
    const int bn   = blockIdx.x * 128;
    const int lrow = lane >> 2;
    const int lkb  = (lane & 3) * 2;
    const uint32_t sb = smem_to_u32(dsm);

    // ldmatrix per-lane address patterns
    // A (16x16 tile): mats {r0-7,k0-7},{r8-15,k0-7},{r0-7,k8-15},{r8-15,k8-15}
    const int arow_pat = (lane & 7) + ((lane >> 3) & 1) * 8;
    const int acol_pat = (lane >> 4) * 8;
    // B (pair of n8k16 tiles): mats {n0-7,k0-7},{n0-7,k8-15},{n8-15,k0-7},{n8-15,k8-15}
    const int brow_pat = (lane & 7) + (lane >> 4) * 8;
    const int bcol_pat = ((lane >> 3) & 1) * 8;

    float acc[4][8][4];
    #pragma unroll
    for (int i = 0; i < 4; i++)
        #pragma unroll
        for (int j = 0; j < 8; j++)
            #pragma unroll
            for (int c = 0; c < 4; c++) acc[i][j][c] = 0.0f;

    const int nCh = K >> 5;

    auto issue = [&](int k0, int st) {
        #pragma unroll
        for (int i = 0; i < 4; i++) {
            const int idx = tid + i * 128;
            const int r   = idx >> 2;
            const int c8  = (idx & 3) * 8;
            const size_t gA = (size_t)(bm + r) * K + k0 + c8;
            const size_t gB = (size_t)(bn + r) * K + k0 + c8;
            const uint32_t so = (uint32_t)((r * SPAD + c8) * 2);
            cp_async16(sb + (0 * 2 + st) * TILE_BYTES + so, Ah + gA);
            cp_async16(sb + (1 * 2 + st) * TILE_BYTES + so, Al + gA);
            cp_async16(sb + (2 * 2 + st) * TILE_BYTES + so, Bh + gB);
        }
        CP_COMMIT();
    };

    issue(0, 0);
    for (int c = 0; c < nCh; c++) {
        if (c + 1 < nCh) { issue((c + 1) << 5, (c + 1) & 1); CP_WAIT1(); }
        else             { CP_WAIT0(); }
        __syncthreads();

        const uint32_t aAh = sb + (0 * 2 + (c & 1)) * TILE_BYTES;
        const uint32_t aAl = sb + (1 * 2 + (c & 1)) * TILE_BYTES;
        const uint32_t aBh = sb + (2 * 2 + (c & 1)) * TILE_BYTES;

        #pragma unroll
        for (int ks = 0; ks < 2; ks++) {
            uint32_t ah[4][4], al[4][4];
            #pragma unroll
            for (int mi = 0; mi < 4; mi++) {
                const uint32_t ra = (uint32_t)(((wm + mi * 16 + arow_pat) * SPAD
                                               + ks * 16 + acol_pat) * 2);
                LDMX4(ah[mi], aAh + ra);
                LDMX4(al[mi], aAl + ra);
            }
            #pragma unroll
            for (int p = 0; p < 4; p++) {
                uint32_t br[4];
                const uint32_t rb = (uint32_t)(((wn + p * 16 + brow_pat) * SPAD
                                               + ks * 16 + bcol_pat) * 2);
                LDMX4(br, aBh + rb);
                #pragma unroll
                for (int mi = 0; mi < 4; mi++) {
                    mma16816(acc[mi][2 * p],     ah[mi], br[0], br[1]);
                    mma16816(acc[mi][2 * p],     al[mi], br[0], br[1]);
                    mma16816(acc[mi][2 * p + 1], ah[mi], br[2], br[3]);
                    mma16816(acc[mi][2 * p + 1], al[mi], br[2], br[3]);
                }
            }
        }
        __syncthreads();
    }

    #pragma unroll
    for (int mi = 0; mi < 4; mi++) {
        const int r0 = bm + wm + mi * 16 + lrow;
        #pragma unroll
        for (int ni = 0; ni < 8; ni++) {
            const int col = bn + wn + ni * 8 + lkb;
            float b0 = 0.f, b1 = 0.f;
            if (hasBias) { b0 = bias[col]; b1 = bias[col + 1]; }
            float2 v0 = make_float2(acc[mi][ni][0] + b0, acc[mi][ni][1] + b1);
            float2 v1 = make_float2(acc[mi][ni][2] + b0, acc[mi][ni][3] + b1);
            *reinterpret_cast<float2*>(&C[(size_t)r0 * N + col])       = v0;
            *reinterpret_cast<float2*>(&C[(size_t)(r0 + 8) * N + col]) = v1;
        }
    }
}

// ---------------------------------------------------------------------------
// Tensor-core causal flash attention (GQA), fp16 2-product + ldmatrix.
// ---------------------------------------------------------------------------
#define APAD 72

__global__ __launch_bounds__(128)
void attn_tc()
{
    __shared__ __half sKh[64][APAD];   // K hi tile (Q hi during prologue)
    __shared__ __half sVh[64][APAD];   // V^T hi tile (Q lo during prologue)

    const int tid  = threadIdx.x;
    const int wid  = tid >> 5;
    const int lane = tid & 31;
    const int g    = lane >> 2;
    const int tig  = lane & 3;
    const int qt   = (int)gridDim.x - 1 - (int)blockIdx.x;
    const int bh   = blockIdx.y;
    const int b    = bh >> 5;
    const int hq   = bh & 31;
    const int n    = hq >> 2;
    const int wm   = wid * 16;

    const uint32_t sK = smem_to_u32(&sKh[0][0]);
    const uint32_t sV = smem_to_u32(&sVh[0][0]);
    const int arow_pat = (lane & 7) + ((lane >> 3) & 1) * 8;
    const int acol_pat = (lane >> 4) * 8;
    const int brow_pat = (lane & 7) + (lane >> 4) * 8;
    const int bcol_pat = ((lane >> 3) & 1) * 8;

    // --- stage Q hi/lo through smem, pull fragments via ldmatrix ---
    const __half* qhb = g_qh + ((size_t)(b * NHQ + hq) * SS + qt * 64) * DK;
    const __half* qlb = g_ql + ((size_t)(b * NHQ + hq) * SS + qt * 64) * DK;
    #pragma unroll
    for (int it = 0; it < 4; it++) {
        const int idx = it * 128 + tid;
        const int r = idx >> 3, c8 = (idx & 7) * 8;
        *reinterpret_cast<uint4*>(&sKh[r][c8]) = *reinterpret_cast<const uint4*>(qhb + r * DK + c8);
        *reinterpret_cast<uint4*>(&sVh[r][c8]) = *reinterpret_cast<const uint4*>(qlb + r * DK + c8);
    }
    __syncthreads();
    uint32_t qh[4][4], ql[4][4];
    #pragma unroll
    for (int ks = 0; ks < 4; ks++) {
        const uint32_t ra = (uint32_t)(((wm + arow_pat) * APAD + ks * 16 + acol_pat) * 2);
        LDMX4(qh[ks], sK + ra);
        LDMX4(ql[ks], sV + ra);
    }

    float oacc[8][4];
    #pragma unroll
    for (int i = 0; i < 8; i++)
        #pragma unroll
        for (int c = 0; c < 4; c++) oacc[i][c] = 0.0f;
    float m0 = -INFINITY, m1 = -INFINITY, l0 = 0.0f, l1 = 0.0f;

    const __half* khb = g_kh  + (size_t)(b * NHKV + n) * SS * DK;
    const __half* vhb = g_vth + (size_t)(b * NHKV + n) * DV * SS;

    for (int kt = 0; kt <= qt; kt++) {
        __syncthreads();
        #pragma unroll
        for (int it = 0; it < 4; it++) {
            const int idx = it * 128 + tid;
            const int r = idx >> 3, c8 = (idx & 7) * 8;
            *reinterpret_cast<uint4*>(&sKh[r][c8]) =
                *reinterpret_cast<const uint4*>(khb + (size_t)(kt * 64 + r) * DK + c8);
            *reinterpret_cast<uint4*>(&sVh[r][c8]) =
                *reinterpret_cast<const uint4*>(vhb + (size_t)r * SS + kt * 64 + c8);
        }
        __syncthreads();

        // ---- S = (Qh + Ql) K^T ----
        float sacc[8][4];
        #pragma unroll
        for (int i = 0; i < 8; i++)
            #pragma unroll
            for (int c = 0; c < 4; c++) sacc[i][c] = 0.0f;

        #pragma unroll
        for (int p = 0; p < 4; p++) {
            #pragma unroll
            for (int ks = 0; ks < 4; ks++) {
                uint32_t kr[4];
                const uint32_t rb = (uint32_t)(((p * 16 + brow_pat) * APAD
                                               + ks * 16 + bcol_pat) * 2);
                LDMX4(kr, sK + rb);
                mma16816(sacc[2 * p],     qh[ks], kr[0], kr[1]);
                mma16816(sacc[2 * p],     ql[ks], kr[0], kr[1]);
                mma16816(sacc[2 * p + 1], qh[ks], kr[2], kr[3]);
                mma16816(sacc[2 * p + 1], ql[ks], kr[2], kr[3]);
            }
        }

        if (kt == qt) {
            #pragma unroll
            for (int ni = 0; ni < 8; ni++) {
                #pragma unroll
                for (int c = 0; c < 4; c++) {
                    const int jl = ni * 8 + tig * 2 + (c & 1);
                    const int il = wm + g + ((c & 2) ? 8 : 0);
                    if (jl > il) sacc[ni][c] = -INFINITY;
                }
            }
        }

        // ---- online softmax ----
        float rmax0 = -INFINITY, rmax1 = -INFINITY;
        #pragma unroll
        for (int ni = 0; ni < 8; ni++) {
            rmax0 = fmaxf(rmax0, fmaxf(sacc[ni][0], sacc[ni][1]));
            rmax1 = fmaxf(rmax1, fmaxf(sacc[ni][2], sacc[ni][3]));
        }
        rmax0 = fmaxf(rmax0, __shfl_xor_sync(0xffffffffu, rmax0, 1));
        rmax0 = fmaxf(rmax0, __shfl_xor_sync(0xffffffffu, rmax0, 2));
        rmax1 = fmaxf(rmax1, __shfl_xor_sync(0xffffffffu, rmax1, 1));
        rmax1 = fmaxf(rmax1, __shfl_xor_sync(0xffffffffu, rmax1, 2));

        const float mn0 = fmaxf(m0, rmax0);
        const float mn1 = fmaxf(m1, rmax1);
        const float cr0 = __expf(m0 - mn0);
        const float cr1 = __expf(m1 - mn1);
        float rs0 = 0.0f, rs1 = 0.0f;
        #pragma unroll
        for (int ni = 0; ni < 8; ni++) {
            float p0 = __expf(sacc[ni][0] - mn0);
            float p1 = __expf(sacc[ni][1] - mn0);
            float p2 = __expf(sacc[ni][2] - mn1);
            float p3 = __expf(sacc[ni][3] - mn1);
            sacc[ni][0] = p0; sacc[ni][1] = p1; sacc[ni][2] = p2; sacc[ni][3] = p3;
            rs0 += p0 + p1;
            rs1 += p2 + p3;
        }
        rs0 += __shfl_xor_sync(0xffffffffu, rs0, 1);
        rs0 += __shfl_xor_sync(0xffffffffu, rs0, 2);
        rs1 += __shfl_xor_sync(0xffffffffu, rs1, 1);
        rs1 += __shfl_xor_sync(0xffffffffu, rs1, 2);
        l0 = l0 * cr0 + rs0;
        l1 = l1 * cr1 + rs1;
        m0 = mn0; m1 = mn1;
        #pragma unroll
        for (int ni = 0; ni < 8; ni++) {
            oacc[ni][0] *= cr0; oacc[ni][1] *= cr0;
            oacc[ni][2] *= cr1; oacc[ni][3] *= cr1;
        }

        // ---- O += (Ph + Pl) V ----
        #pragma unroll
        for (int ks = 0; ks < 4; ks++) {
            uint32_t ph[4], pl[4];
            split_pack(sacc[2 * ks][0],     sacc[2 * ks][1],     ph[0], pl[0]);
            split_pack(sacc[2 * ks][2],     sacc[2 * ks][3],     ph[1], pl[1]);
            split_pack(sacc[2 * ks + 1][0], sacc[2 * ks + 1][1], ph[2], pl[2]);
            split_pack(sacc[2 * ks + 1][2], sacc[2 * ks + 1][3], ph[3], pl[3]);
            #pragma unroll
            for (int p = 0; p < 4; p++) {
                uint32_t vr[4];
                const uint32_t rb = (uint32_t)(((p * 16 + brow_pat) * APAD
                                               + ks * 16 + bcol_pat) * 2);
                LDMX4(vr, sV + rb);
                mma16816(oacc[2 * p],     ph, vr[0], vr[1]);
                mma16816(oacc[2 * p],     pl, vr[0], vr[1]);
                mma16816(oacc[2 * p + 1], ph, vr[2], vr[3]);
                mma16816(oacc[2 * p + 1], pl, vr[2], vr[3]);
            }
        }
    }

    // ---- epilogue: normalize + split hi/lo into gemm2 A buffers ----
    const float inv0 = 1.0f / l0;
    const float inv1 = 1.0f / l1;
    const size_t r0g = (size_t)(b * SS + qt * 64 + wm + g);
    const size_t r1g = r0g + 8;
    #pragma unroll
    for (int ni = 0; ni < 8; ni++) {
        const int col = hq * DV + ni * 8 + tig * 2;
        uint32_t hi, lo;
        split_pack(oacc[ni][0] * inv0, oacc[ni][1] * inv0, hi, lo);
        *reinterpret_cast<uint32_t*>(&g_ah[r0g * HH + col]) = hi;
        *reinterpret_cast<uint32_t*>(&g_al[r0g * HH + col]) = lo;
        split_pack(oacc[ni][2] * inv1, oacc[ni][3] * inv1, hi, lo);
        *reinterpret_cast<uint32_t*>(&g_ah[r1g * HH + col]) = hi;
        *reinterpret_cast<uint32_t*>(&g_al[r1g * HH + col]) = lo;
    }
}

// ---------------------------------------------------------------------------
// Launcher
// ---------------------------------------------------------------------------
extern "C" void kernel_launch(void* const* d_in, const int* in_sizes, int n_in,
                              void* d_out, int out_size)
{
    const float* x     = (const float*)d_in[0];
    const float* Wqkv  = (const float*)d_in[1];
    const float* Wout  = (const float*)d_in[2];
    const float* b_out = (const float*)d_in[3];
    float* out = (float*)d_out;

    float* qkv_p;
    __half *ah_p, *al_p, *wqh_p, *woh_p;
    cudaGetSymbolAddress((void**)&qkv_p, g_qkv);
    cudaGetSymbolAddress((void**)&ah_p,  g_ah);
    cudaGetSymbolAddress((void**)&al_p,  g_al);
    cudaGetSymbolAddress((void**)&wqh_p, g_wqh);
    cudaGetSymbolAddress((void**)&woh_p, g_woh);

    cudaFuncSetAttribute(gemm_hmma, cudaFuncAttributeMaxDynamicSharedMemorySize,
                         GSMEM_BYTES);

    // Prep: split x (hi/lo); transpose weights (hi only)
    {
        const int n = MM * HH;
        split_f32<<<n / (256 * 4), 256>>>(x, ah_p, al_p, n);
    }
    transpose_h<<<dim3(QKV_OUT / 32, HH / 32), dim3(32, 8)>>>(Wqkv, wqh_p, HH, QKV_OUT);
    transpose_h<<<dim3(HH / 32, HH / 32), dim3(32, 8)>>>(Wout, woh_p, HH, HH);

    // 1) QKV projection
    gemm_hmma<<<dim3(QKV_OUT / 128, MM / 128), 128, GSMEM_BYTES>>>(
        ah_p, al_p, wqh_p, qkv_p, nullptr, MM, QKV_OUT, HH, 0);

    // 2) Split Q (hi/lo, scaled) + K (hi); transpose V (hi)
    split_qk<<<(MM * 2560 / 4) / 256, 256>>>();
    transpose_v<<<dim3(SS / 32, DV / 32, BB * NHKV), dim3(32, 8)>>>();

    // 3) Tensor-core flash attention -> writes g_ah/g_al
    attn_tc<<<dim3(SS / 64, BB * NHQ), 128>>>();

    // 4) Output projection + bias
    gemm_hmma<<<dim3(HH / 128, MM / 128), 128, GSMEM_BYTES>>>(
        ah_p, al_p, woh_p, out, b_out, MM, HH, HH, 1);
}